// round 10
// baseline (speedup 1.0000x reference)
#include <cuda_runtime.h>
#include <cuda_bf16.h>
#include <math.h>
#include <float.h>
#include <stdint.h>

#define N_ 64
#define C_ 256
#define S_ 64
#define P_ 16
#define K_ 4
#define H_ 4
#define D_ 64
#define B_  (N_*P_)    /* 1024 */
#define BS_ (B_*S_)    /* 65536 */

// ---------------- scratch (static __device__, no allocations) ----------------
__device__ float g_X2 [BS_*C_];            // x2: (b, s, c) fp32
__device__ __nv_bfloat16 g_X2h[BS_*C_];    // bf16 hi of X2
__device__ __nv_bfloat16 g_X2l[BS_*C_];    // bf16 lo of X2
__device__ __nv_bfloat16 g_QKVh[3*BS_*C_]; // Q/K/V hi (mat-major)
__device__ __nv_bfloat16 g_QKVl[3*BS_*C_]; // Q/K/V lo
__device__ __nv_bfloat16 g_ATTh[BS_*C_];   // attention out (hi)
__device__ __nv_bfloat16 g_ATTl[BS_*C_];   // attention out (lo)
__device__ __nv_bfloat16 g_Wth[4*C_*C_];   // transposed weights hi: [mat][n][k]
__device__ __nv_bfloat16 g_Wtl[4*C_*C_];
__device__ int   g_idx[P_*N_*S_];
__device__ float g_clu[P_*N_*K_*C_];

// ---------------- helpers ----------------
__device__ __forceinline__ uint32_t smem_u32(const void* p) {
    uint32_t a;
    asm("{ .reg .u64 t; cvta.to.shared.u64 t, %1; cvt.u32.u64 %0, t; }" : "=r"(a) : "l"(p));
    return a;
}
__device__ __forceinline__ void ldsm4(uint32_t* r, uint32_t addr) {
    asm volatile("ldmatrix.sync.aligned.m8n8.x4.shared.b16 {%0,%1,%2,%3}, [%4];"
                 : "=r"(r[0]), "=r"(r[1]), "=r"(r[2]), "=r"(r[3]) : "r"(addr));
}
__device__ __forceinline__ void mma16816(float* d, const uint32_t* a, uint32_t b0, uint32_t b1) {
    asm volatile("mma.sync.aligned.m16n8k16.row.col.f32.bf16.bf16.f32 "
                 "{%0,%1,%2,%3}, {%4,%5,%6,%7}, {%8,%9}, {%0,%1,%2,%3};"
                 : "+f"(d[0]), "+f"(d[1]), "+f"(d[2]), "+f"(d[3])
                 : "r"(a[0]), "r"(a[1]), "r"(a[2]), "r"(a[3]), "r"(b0), "r"(b1));
}
__device__ __forceinline__ void cpasync16(uint32_t saddr, const void* g) {
    asm volatile("cp.async.cg.shared.global [%0], [%1], 16;" :: "r"(saddr), "l"(g) : "memory");
}
__device__ __forceinline__ void split_bf(float x, __nv_bfloat16& h, __nv_bfloat16& l) {
    h = __float2bfloat16_rn(x);
    l = __float2bfloat16_rn(x - __bfloat162float(h));
}
__device__ __forceinline__ void split2(float a, float b, uint32_t& h2, uint32_t& l2) {
    __nv_bfloat16 ha, la, hb, lb;
    split_bf(a, ha, la);
    split_bf(b, hb, lb);
    __nv_bfloat162 Hp; Hp.x = ha; Hp.y = hb;
    __nv_bfloat162 Lp; Lp.x = la; Lp.y = lb;
    h2 = *(uint32_t*)&Hp;
    l2 = *(uint32_t*)&Lp;
}

// ---------------- 1. transpose x(n,c,s,p) -> X2(n*16+p, s, c) + bf16 hi/lo ----------------
__global__ __launch_bounds__(256) void transpose_kernel(const float* __restrict__ x) {
    extern __shared__ float Ts[]; // [16][1025]
    int n  = blockIdx.x >> 4;
    int c0 = (blockIdx.x & 15) * 16;
    int t = threadIdx.x;
    const float* src = x + (size_t)(n*C_ + c0) * (S_*P_);
    for (int idx = t; idx < 16*1024; idx += 256) {
        int i = idx >> 10, sp = idx & 1023;
        Ts[i*1025 + sp] = src[i*1024 + sp];
    }
    __syncthreads();
    for (int idx = t; idx < 16*1024; idx += 256) {
        int sp = idx >> 4, i = idx & 15;
        int s = sp >> 4, p = sp & 15;
        size_t g = (size_t)((n*P_ + p)*S_ + s) * C_ + c0 + i;
        float v = Ts[i*1025 + sp];
        g_X2[g] = v;
        __nv_bfloat16 h, l; split_bf(v, h, l);
        g_X2h[g] = h;
        g_X2l[g] = l;
    }
}

// ---------------- 1b. weight transpose + hi/lo conversion ----------------
__global__ __launch_bounds__(256) void wconv_kernel(const float* __restrict__ Wq,
                                                    const float* __restrict__ Wk,
                                                    const float* __restrict__ Wv,
                                                    const float* __restrict__ Wo) {
    int g = blockIdx.x*256 + threadIdx.x;   // 0..262143
    int mat = g >> 16, rem = g & 65535;
    int n = rem >> 8, k = rem & 255;
    const float* W = (mat==0) ? Wq : (mat==1) ? Wk : (mat==2) ? Wv : Wo;
    float v = W[k*256 + n];
    __nv_bfloat16 h, l; split_bf(v, h, l);
    g_Wth[mat*65536 + n*256 + k] = h;
    g_Wtl[mat*65536 + n*256 + k] = l;
}

// ---------------- 2. instance-norm + cosine-sim argmax -> hard_idx ----------------
__global__ __launch_bounds__(256) void assign_kernel(const float* __restrict__ protos) {
    extern __shared__ float sm[];
    float* Xs   = sm;                // 64 x 260
    float* Ps   = Xs + 64*260;       // 4 x 256
    float* mu   = Ps + 4*256;        // 256
    float* rstd = mu + 256;          // 256
    float* rn   = rstd + 256;        // 4
    int p = blockIdx.x & 15;
    int n = blockIdx.x >> 4;
    int b = n*16 + p;
    int t = threadIdx.x;
    const float* xb = g_X2 + (size_t)b * S_ * C_;
    for (int idx = t; idx < S_*C_; idx += 256) {
        int s = idx >> 8, c = idx & 255;
        Xs[s*260 + c] = xb[idx];
    }
    for (int idx = t; idx < K_*C_; idx += 256)
        Ps[idx] = protos[p*K_*C_ + idx];
    __syncthreads();

    int w = t >> 5, lane = t & 31;
    if (w < 4) {
        float ss = 0.f;
        for (int c = lane; c < 256; c += 32) { float v = Ps[w*256 + c]; ss += v*v; }
        #pragma unroll
        for (int o = 16; o; o >>= 1) ss += __shfl_xor_sync(0xffffffffu, ss, o);
        if (lane == 0) rn[w] = rsqrtf(ss);
    }
    {
        int c = t;
        float s1 = 0.f;
        #pragma unroll 8
        for (int s = 0; s < 64; s++) s1 += Xs[s*260 + c];
        float m = s1 * (1.f/64.f);
        float s2 = 0.f;
        #pragma unroll 8
        for (int s = 0; s < 64; s++) { float d = Xs[s*260 + c] - m; s2 += d*d; }
        mu[c] = m;
        rstd[c] = rsqrtf(s2 * (1.f/64.f) + 1e-5f);
    }
    __syncthreads();

    int s = t >> 2, j = t & 3;
    float a0 = 0.f, a1 = 0.f, a2 = 0.f, a3 = 0.f;
    for (int cc = 0; cc < 64; cc++) {
        int c = cc*4 + j;
        float xv = (Xs[s*260 + c] - mu[c]) * rstd[c];
        a0 += xv * Ps[c];
        a1 += xv * Ps[256 + c];
        a2 += xv * Ps[512 + c];
        a3 += xv * Ps[768 + c];
    }
    #pragma unroll
    for (int o = 1; o <= 2; o <<= 1) {
        a0 += __shfl_xor_sync(0xffffffffu, a0, o);
        a1 += __shfl_xor_sync(0xffffffffu, a1, o);
        a2 += __shfl_xor_sync(0xffffffffu, a2, o);
        a3 += __shfl_xor_sync(0xffffffffu, a3, o);
    }
    if (j == 0) {
        float v0 = a0*rn[0], v1 = a1*rn[1], v2 = a2*rn[2], v3 = a3*rn[3];
        int best = 0; float bv = v0;
        if (v1 > bv) { bv = v1; best = 1; }
        if (v2 > bv) { bv = v2; best = 2; }
        if (v3 > bv) { bv = v3; best = 3; }
        g_idx[(p*N_ + n)*S_ + s] = best;
    }
}

// ---------------- 3. per-(n,s) mode over parts ----------------
__global__ __launch_bounds__(256) void mode_kernel(float* __restrict__ out) {
    int t = blockIdx.x*256 + threadIdx.x;   // n*64 + s
    if (t >= N_*S_) return;
    int n = t >> 6, s = t & 63;
    int c0=0,c1=0,c2=0,c3=0;
    #pragma unroll
    for (int p = 0; p < 16; p++) {
        int k = g_idx[(p*N_ + n)*S_ + s];
        c0 += (k==0); c1 += (k==1); c2 += (k==2); c3 += (k==3);
    }
    int best = 0, bc = c0;
    if (c1 > bc) { bc = c1; best = 1; }
    if (c2 > bc) { bc = c2; best = 2; }
    if (c3 > bc) { bc = c3; best = 3; }
    out[N_*C_*P_ + t] = (float)best;
}

// ---------------- 4. HMMA split-bf16 GEMM: CTA tile 64(M) x 128(N), 2 CTAs/SM ----------------
#define STG_AH 0
#define STG_AL 8192
#define STG_BH 16384
#define STG_BL 32768
#define STG_SZ 49152
#define GEMM_SMEM (2*STG_SZ)

__device__ __forceinline__ void gemm_mainloop(
    const __nv_bfloat16* __restrict__ Ah, const __nv_bfloat16* __restrict__ Al,
    const __nv_bfloat16* __restrict__ Bth, const __nv_bfloat16* __restrict__ Btl,
    char* smc, int m0, int n0, int tid, int wm, int wn, int lane,
    float acc[2][4][4])
{
    uint32_t sbase = smem_u32(smc);
    #pragma unroll
    for (int i = 0; i < 2; i++)
        #pragma unroll
        for (int j = 0; j < 4; j++)
            #pragma unroll
            for (int q = 0; q < 4; q++) acc[i][j][q] = 0.f;

    auto issue = [&](int kc, int stage) {
        int k0 = kc * 64;
        uint32_t st = sbase + stage*STG_SZ;
        #pragma unroll
        for (int it = 0; it < 2; it++) {
            int idx = tid + it*256;
            int row = idx >> 3, v = idx & 7;
            uint32_t off = (uint32_t)(row*128 + v*16);
            uint32_t sw = off ^ ((off >> 3) & 0x70);
            size_t ga = (size_t)(m0 + row)*256 + k0 + v*8;
            cpasync16(st + STG_AH + sw, Ah + ga);
            cpasync16(st + STG_AL + sw, Al + ga);
        }
        #pragma unroll
        for (int it = 0; it < 4; it++) {
            int idx = tid + it*256;
            int row = idx >> 3, v = idx & 7;
            uint32_t off = (uint32_t)(row*128 + v*16);
            uint32_t sw = off ^ ((off >> 3) & 0x70);
            size_t gb = (size_t)(n0 + row)*256 + k0 + v*8;
            cpasync16(st + STG_BH + sw, Bth + gb);
            cpasync16(st + STG_BL + sw, Btl + gb);
        }
        asm volatile("cp.async.commit_group;" ::: "memory");
    };

    issue(0, 0);

    for (int kc = 0; kc < 4; kc++) {
        if (kc < 3) {
            issue(kc + 1, (kc + 1) & 1);
            asm volatile("cp.async.wait_group 1;" ::: "memory");
        } else {
            asm volatile("cp.async.wait_group 0;" ::: "memory");
        }
        __syncthreads();

        uint32_t st = sbase + (kc & 1)*STG_SZ;
        uint32_t sAh = st + STG_AH, sAl = st + STG_AL;
        uint32_t sBh = st + STG_BH, sBl = st + STG_BL;

        #pragma unroll
        for (int kk = 0; kk < 4; kk++) {
            uint32_t ah[2][4], al[2][4];
            #pragma unroll
            for (int mi = 0; mi < 2; mi++) {
                int r = wm*32 + mi*16 + (lane & 15);
                uint32_t off = (uint32_t)(r*128 + kk*32 + ((lane >> 4) & 1)*16);
                off ^= (off >> 3) & 0x70;
                ldsm4(ah[mi], sAh + off);
                ldsm4(al[mi], sAl + off);
            }
            uint32_t bh[2][4], bl[2][4];
            #pragma unroll
            for (int ni2 = 0; ni2 < 2; ni2++) {
                int r = wn*32 + ni2*16 + ((lane >> 4) & 1)*8 + (lane & 7);
                uint32_t off = (uint32_t)(r*128 + kk*32 + ((lane >> 3) & 1)*16);
                off ^= (off >> 3) & 0x70;
                ldsm4(bh[ni2], sBh + off);
                ldsm4(bl[ni2], sBl + off);
            }
            #pragma unroll
            for (int mi = 0; mi < 2; mi++) {
                #pragma unroll
                for (int ni = 0; ni < 4; ni++) {
                    int ni2 = ni >> 1, hf = (ni & 1)*2;
                    mma16816(acc[mi][ni], ah[mi], bh[ni2][hf], bh[ni2][hf+1]);
                    mma16816(acc[mi][ni], ah[mi], bl[ni2][hf], bl[ni2][hf+1]);
                    mma16816(acc[mi][ni], al[mi], bh[ni2][hf], bh[ni2][hf+1]);
                }
            }
        }
        __syncthreads();
    }
}

// QKV variant: bf16 hi/lo epilogue into g_QKVh/l, mat = n0>>8
__global__ __launch_bounds__(256, 2) void mma_gemm_kernel(
    const __nv_bfloat16* __restrict__ Ah, const __nv_bfloat16* __restrict__ Al,
    const __nv_bfloat16* __restrict__ Bth, const __nv_bfloat16* __restrict__ Btl,
    const float* __restrict__ b0p, const float* __restrict__ b1p, const float* __restrict__ b2p,
    __nv_bfloat16* __restrict__ outH, __nv_bfloat16* __restrict__ outL)
{
    extern __shared__ char smc[];
    int tid = threadIdx.x;
    int wid = tid >> 5, lane = tid & 31;
    int wm = wid >> 2, wn = wid & 3;
    int m0 = blockIdx.x * 64;
    int n0 = blockIdx.y * 128;

    float acc[2][4][4];
    gemm_mainloop(Ah, Al, Bth, Btl, smc, m0, n0, tid, wm, wn, lane, acc);

    int trow = lane >> 2, tcol = (lane & 3)*2;
    int mat = n0 >> 8;
    const float* bias = (mat == 0) ? b0p : (mat == 1) ? b1p : b2p;
    int clbase = (n0 & 255) + wn*32 + tcol;
    size_t moff = (size_t)mat * BS_ * C_;
    #pragma unroll
    for (int mi = 0; mi < 2; mi++) {
        #pragma unroll
        for (int ni = 0; ni < 4; ni++) {
            int cl = clbase + ni*8;
            size_t r0 = (size_t)(m0 + wm*32 + mi*16 + trow);
            size_t r1 = r0 + 8;
            float v0x = acc[mi][ni][0] + bias[cl];
            float v0y = acc[mi][ni][1] + bias[cl+1];
            float v1x = acc[mi][ni][2] + bias[cl];
            float v1y = acc[mi][ni][3] + bias[cl+1];
            uint32_t h2, l2;
            split2(v0x, v0y, h2, l2);
            *(uint32_t*)(outH + moff + r0*256 + cl) = h2;
            *(uint32_t*)(outL + moff + r0*256 + cl) = l2;
            split2(v1x, v1y, h2, l2);
            *(uint32_t*)(outH + moff + r1*256 + cl) = h2;
            *(uint32_t*)(outL + moff + r1*256 + cl) = l2;
        }
    }
}

// Wo variant: bias + residual, fused assignment-max pooling (one b per CTA)
#define TS_STRIDE 132
__global__ __launch_bounds__(256, 2) void mma_gemm_wo_kernel(
    const __nv_bfloat16* __restrict__ Ah, const __nv_bfloat16* __restrict__ Al,
    const __nv_bfloat16* __restrict__ Bth, const __nv_bfloat16* __restrict__ Btl,
    const float* __restrict__ bias, const float* __restrict__ res)
{
    extern __shared__ char smc[];
    int tid = threadIdx.x;
    int wid = tid >> 5, lane = tid & 31;
    int wm = wid >> 2, wn = wid & 3;
    int m0 = blockIdx.x * 64;
    int n0 = blockIdx.y * 128;

    float acc[2][4][4];
    gemm_mainloop(Ah, Al, Bth, Btl, smc, m0, n0, tid, wm, wn, lane, acc);

    float* TS = (float*)smc;                        // [64][TS_STRIDE]
    int* idxs = (int*)(smc + 64*TS_STRIDE*4);       // [64]
    int trow = lane >> 2, tcol = (lane & 3)*2;
    #pragma unroll
    for (int mi = 0; mi < 2; mi++) {
        #pragma unroll
        for (int ni = 0; ni < 4; ni++) {
            int lc = wn*32 + ni*8 + tcol;
            int lr0 = wm*32 + mi*16 + trow;
            int lr1 = lr0 + 8;
            int gc = n0 + lc;
            size_t r0 = (size_t)(m0 + lr0), r1 = (size_t)(m0 + lr1);
            float2 a0 = *(const float2*)(res + r0*256 + gc);
            float2 a1 = *(const float2*)(res + r1*256 + gc);
            TS[lr0*TS_STRIDE + lc]     = acc[mi][ni][0] + bias[gc]   + a0.x;
            TS[lr0*TS_STRIDE + lc + 1] = acc[mi][ni][1] + bias[gc+1] + a0.y;
            TS[lr1*TS_STRIDE + lc]     = acc[mi][ni][2] + bias[gc]   + a1.x;
            TS[lr1*TS_STRIDE + lc + 1] = acc[mi][ni][3] + bias[gc+1] + a1.y;
        }
    }
    int b = m0 >> 6;                 // one (n,p) per CTA
    int n = b >> 4, p = b & 15;
    if (tid < 64)
        idxs[tid] = g_idx[(p*N_ + n)*S_ + tid];
    __syncthreads();

    if (tid < 128) {
        int cl = tid;
        float m[4] = {-FLT_MAX, -FLT_MAX, -FLT_MAX, -FLT_MAX};
        int cnt[4] = {0, 0, 0, 0};
        #pragma unroll 8
        for (int s = 0; s < 64; s++) {
            float v = TS[s*TS_STRIDE + cl];
            int k = idxs[s];
            m[k] = fmaxf(m[k], v);
            cnt[k]++;
        }
        size_t cbase = ((size_t)(p*N_ + n)*4)*256 + n0 + cl;
        #pragma unroll
        for (int k = 0; k < 4; k++) {
            float r = (cnt[k] == 64) ? m[k] : fmaxf(m[k], 0.f);
            g_clu[cbase + (size_t)k*256] = r;
        }
    }
}

// ---------------- 5. HMMA causal attention with causal block-skip ----------------
#define AQH 0
#define AQL 8192
#define AKH 16384
#define AKL 24576
#define AVH 32768
#define AVL 40960

__global__ __launch_bounds__(128) void attn_mma_kernel() {
    __shared__ __align__(16) char smem[49152];
    int bb = blockIdx.x >> 2, h = blockIdx.x & 3;
    int tid = threadIdx.x, lane = tid & 31, wq = tid >> 5;
    size_t gbase = (size_t)bb*64*256 + h*64;

    for (int i = tid; i < 2048; i += 128) {
        int arr = i >> 9, c = i & 511;
        int s = c >> 3, db = c & 7;
        const __nv_bfloat16* src = (arr & 1 ? g_QKVl : g_QKVh) + (size_t)(arr >> 1)*BS_*C_;
        uint32_t off = (uint32_t)(s*128 + db*16);
        off ^= (off >> 3) & 0x70;
        *(uint4*)(smem + arr*8192 + off) = *(const uint4*)(src + gbase + (size_t)s*256 + db*8);
    }
    for (int i = tid; i < 1024; i += 128) {
        int hl = i >> 9, c = i & 511;
        int s = c >> 3, db = c & 7;
        const __nv_bfloat16* src = (hl ? g_QKVl : g_QKVh) + (size_t)2*BS_*C_;
        uint4 pk = *(const uint4*)(src + gbase + (size_t)s*256 + db*8);
        const __nv_bfloat16* e = (const __nv_bfloat16*)&pk;
        #pragma unroll
        for (int j = 0; j < 8; j++) {
            uint32_t off = (uint32_t)((db*8 + j)*128 + s*2);
            off ^= (off >> 3) & 0x70;
            *(__nv_bfloat16*)(smem + AVH + hl*8192 + off) = e[j];
        }
    }
    __syncthreads();

    uint32_t sQh = smem_u32(smem + AQH), sQl = smem_u32(smem + AQL);
    uint32_t sKh = smem_u32(smem + AKH), sKl = smem_u32(smem + AKL);
    uint32_t sVh = smem_u32(smem + AVH), sVl = smem_u32(smem + AVL);

    float sc[8][4];
    #pragma unroll
    for (int i = 0; i < 8; i++)
        #pragma unroll
        for (int j = 0; j < 4; j++) sc[i][j] = 0.f;

    #pragma unroll
    for (int kk = 0; kk < 4; kk++) {
        uint32_t qh[4], ql[4];
        {
            int r = wq*16 + (lane & 15);
            uint32_t off = (uint32_t)(r*128 + kk*32 + ((lane >> 4) & 1)*16);
            off ^= (off >> 3) & 0x70;
            ldsm4(qh, sQh + off);
            ldsm4(ql, sQl + off);
        }
        #pragma unroll
        for (int ni2 = 0; ni2 < 4; ni2++) {
            if (ni2 <= wq) {   // causal: K-blocks beyond the diagonal are fully masked
                uint32_t kh[4], kl[4];
                int r = ni2*16 + ((lane >> 4) & 1)*8 + (lane & 7);
                uint32_t off = (uint32_t)(r*128 + kk*32 + ((lane >> 3) & 1)*16);
                off ^= (off >> 3) & 0x70;
                ldsm4(kh, sKh + off);
                ldsm4(kl, sKl + off);
                mma16816(sc[2*ni2],   qh, kh[0], kh[1]);
                mma16816(sc[2*ni2],   qh, kl[0], kl[1]);
                mma16816(sc[2*ni2],   ql, kh[0], kh[1]);
                mma16816(sc[2*ni2+1], qh, kh[2], kh[3]);
                mma16816(sc[2*ni2+1], qh, kl[2], kl[3]);
                mma16816(sc[2*ni2+1], ql, kh[2], kh[3]);
            }
        }
    }

    int trow = lane >> 2, tcolb = (lane & 3)*2;
    int q0 = wq*16 + trow, q1 = q0 + 8;
    float mx0 = -FLT_MAX, mx1 = -FLT_MAX;
    #pragma unroll
    for (int ni = 0; ni < 8; ni++) {
        int c0 = ni*8 + tcolb, c1 = c0 + 1;
        float v0 = (c0 <= q0) ? sc[ni][0]*0.125f : -FLT_MAX;
        float v1 = (c1 <= q0) ? sc[ni][1]*0.125f : -FLT_MAX;
        float v2 = (c0 <= q1) ? sc[ni][2]*0.125f : -FLT_MAX;
        float v3 = (c1 <= q1) ? sc[ni][3]*0.125f : -FLT_MAX;
        sc[ni][0] = v0; sc[ni][1] = v1; sc[ni][2] = v2; sc[ni][3] = v3;
        mx0 = fmaxf(mx0, fmaxf(v0, v1));
        mx1 = fmaxf(mx1, fmaxf(v2, v3));
    }
    mx0 = fmaxf(mx0, __shfl_xor_sync(0xffffffffu, mx0, 1));
    mx0 = fmaxf(mx0, __shfl_xor_sync(0xffffffffu, mx0, 2));
    mx1 = fmaxf(mx1, __shfl_xor_sync(0xffffffffu, mx1, 1));
    mx1 = fmaxf(mx1, __shfl_xor_sync(0xffffffffu, mx1, 2));
    float s0 = 0.f, s1 = 0.f;
    #pragma unroll
    for (int ni = 0; ni < 8; ni++) {
        float e0 = (sc[ni][0] > -FLT_MAX) ? expf(sc[ni][0] - mx0) : 0.f;
        float e1 = (sc[ni][1] > -FLT_MAX) ? expf(sc[ni][1] - mx0) : 0.f;
        float e2 = (sc[ni][2] > -FLT_MAX) ? expf(sc[ni][2] - mx1) : 0.f;
        float e3 = (sc[ni][3] > -FLT_MAX) ? expf(sc[ni][3] - mx1) : 0.f;
        sc[ni][0] = e0; sc[ni][1] = e1; sc[ni][2] = e2; sc[ni][3] = e3;
        s0 += e0 + e1;
        s1 += e2 + e3;
    }
    s0 += __shfl_xor_sync(0xffffffffu, s0, 1);
    s0 += __shfl_xor_sync(0xffffffffu, s0, 2);
    s1 += __shfl_xor_sync(0xffffffffu, s1, 1);
    s1 += __shfl_xor_sync(0xffffffffu, s1, 2);
    float i0 = 1.f/s0, i1 = 1.f/s1;
    #pragma unroll
    for (int ni = 0; ni < 8; ni++) {
        sc[ni][0] *= i0; sc[ni][1] *= i0;
        sc[ni][2] *= i1; sc[ni][3] *= i1;
    }

    float o[8][4];
    #pragma unroll
    for (int i = 0; i < 8; i++)
        #pragma unroll
        for (int j = 0; j < 4; j++) o[i][j] = 0.f;

    #pragma unroll
    for (int kt = 0; kt < 4; kt++) {
        if (kt <= wq) {   // causal: P blocks beyond the diagonal are identically zero
            uint32_t ph[4], pl[4];
            split2(sc[2*kt][0],   sc[2*kt][1],   ph[0], pl[0]);
            split2(sc[2*kt][2],   sc[2*kt][3],   ph[1], pl[1]);
            split2(sc[2*kt+1][0], sc[2*kt+1][1], ph[2], pl[2]);
            split2(sc[2*kt+1][2], sc[2*kt+1][3], ph[3], pl[3]);
            #pragma unroll
            for (int ni2 = 0; ni2 < 4; ni2++) {
                uint32_t vh[4], vl[4];
                int r = ni2*16 + ((lane >> 4) & 1)*8 + (lane & 7);
                uint32_t off = (uint32_t)(r*128 + kt*32 + ((lane >> 3) & 1)*16);
                off ^= (off >> 3) & 0x70;
                ldsm4(vh, sVh + off);
                ldsm4(vl, sVl + off);
                mma16816(o[2*ni2],   ph, vh[0], vh[1]);
                mma16816(o[2*ni2],   ph, vl[0], vl[1]);
                mma16816(o[2*ni2],   pl, vh[0], vh[1]);
                mma16816(o[2*ni2+1], ph, vh[2], vh[3]);
                mma16816(o[2*ni2+1], ph, vl[2], vl[3]);
                mma16816(o[2*ni2+1], pl, vh[2], vh[3]);
            }
        }
    }

    size_t r0 = (size_t)bb*64 + wq*16 + trow;
    size_t r1 = r0 + 8;
    #pragma unroll
    for (int ni = 0; ni < 8; ni++) {
        int c = h*64 + ni*8 + tcolb;
        uint32_t h2, l2;
        split2(o[ni][0], o[ni][1], h2, l2);
        *(uint32_t*)(g_ATTh + r0*256 + c) = h2;
        *(uint32_t*)(g_ATTl + r0*256 + c) = l2;
        split2(o[ni][2], o[ni][3], h2, l2);
        *(uint32_t*)(g_ATTh + r1*256 + c) = h2;
        *(uint32_t*)(g_ATTl + r1*256 + c) = l2;
    }
}

// ---------------- 7. per-part FC: 256 blocks (p x 16 col-tiles) ----------------
__global__ __launch_bounds__(256) void fc_kernel(const float* __restrict__ fcb,
                                                 float* __restrict__ out) {
    __shared__ float As[32*68];
    __shared__ float Bs[32*17];
    int p  = blockIdx.x >> 4;
    int o0 = (blockIdx.x & 15) * 16;
    int t = threadIdx.x;
    int tm = t >> 4, tn = t & 15;
    const float* Ap = g_clu + (size_t)p*N_*1024;
    const float* Bp = fcb  + (size_t)p*1024*256;
    float acc[4] = {0.f, 0.f, 0.f, 0.f};

    for (int k0 = 0; k0 < 1024; k0 += 32) {
        #pragma unroll
        for (int i = 0; i < 8; i++) {
            int e = t + i*256;
            int row = e >> 5, kk = e & 31;
            As[kk*68 + row] = Ap[(size_t)row*1024 + k0 + kk];
        }
        #pragma unroll
        for (int i = 0; i < 2; i++) {
            int e = t + i*256;
            int kk = e >> 4, oc = e & 15;
            Bs[kk*17 + oc] = Bp[(size_t)(k0 + kk)*256 + o0 + oc];
        }
        __syncthreads();
        #pragma unroll
        for (int kk = 0; kk < 32; kk++) {
            float4 a4 = *(const float4*)&As[kk*68 + tm*4];
            float b = Bs[kk*17 + tn];
            acc[0] += a4.x*b; acc[1] += a4.y*b; acc[2] += a4.z*b; acc[3] += a4.w*b;
        }
        __syncthreads();
    }
    #pragma unroll
    for (int i = 0; i < 4; i++) {
        int nrow = tm*4 + i;
        out[(size_t)nrow*C_*P_ + (o0 + tn)*P_ + p] = acc[i];
    }
}

// ---------------- launch ----------------
extern "C" void kernel_launch(void* const* d_in, const int* in_sizes, int n_in,
                              void* d_out, int out_size) {
    const float* x      = (const float*)d_in[0];
    const float* protos = (const float*)d_in[1];
    const float* Wq = (const float*)d_in[2];
    const float* bq = (const float*)d_in[3];
    const float* Wk = (const float*)d_in[4];
    const float* bk = (const float*)d_in[5];
    const float* Wv = (const float*)d_in[6];
    const float* bv = (const float*)d_in[7];
    const float* Wo = (const float*)d_in[8];
    const float* bo = (const float*)d_in[9];
    const float* fcb = (const float*)d_in[10];
    float* out = (float*)d_out;

    float *pX2;
    __nv_bfloat16 *pX2h, *pX2l, *pATTh, *pATTl, *pWth, *pWtl, *pQKVh, *pQKVl;
    cudaGetSymbolAddress((void**)&pX2,   g_X2);
    cudaGetSymbolAddress((void**)&pX2h,  g_X2h);
    cudaGetSymbolAddress((void**)&pX2l,  g_X2l);
    cudaGetSymbolAddress((void**)&pATTh, g_ATTh);
    cudaGetSymbolAddress((void**)&pATTl, g_ATTl);
    cudaGetSymbolAddress((void**)&pWth,  g_Wth);
    cudaGetSymbolAddress((void**)&pWtl,  g_Wtl);
    cudaGetSymbolAddress((void**)&pQKVh, g_QKVh);
    cudaGetSymbolAddress((void**)&pQKVl, g_QKVl);

    static cudaStream_t s1 = nullptr;
    static cudaEvent_t e0 = nullptr, eT = nullptr, eA = nullptr, eO = nullptr;
    if (!s1) {
        cudaStreamCreateWithFlags(&s1, cudaStreamNonBlocking);
        cudaEventCreateWithFlags(&e0, cudaEventDisableTiming);
        cudaEventCreateWithFlags(&eT, cudaEventDisableTiming);
        cudaEventCreateWithFlags(&eA, cudaEventDisableTiming);
        cudaEventCreateWithFlags(&eO, cudaEventDisableTiming);
    }

    const int TR_SMEM  = 16*1025*4;                          // 65600
    const int AS_SMEM  = (64*260 + 4*256 + 256 + 256 + 4)*4; // 72720
    cudaFuncSetAttribute(transpose_kernel,   cudaFuncAttributeMaxDynamicSharedMemorySize, TR_SMEM);
    cudaFuncSetAttribute(assign_kernel,      cudaFuncAttributeMaxDynamicSharedMemorySize, AS_SMEM);
    cudaFuncSetAttribute(mma_gemm_kernel,    cudaFuncAttributeMaxDynamicSharedMemorySize, GEMM_SMEM);
    cudaFuncSetAttribute(mma_gemm_wo_kernel, cudaFuncAttributeMaxDynamicSharedMemorySize, GEMM_SMEM);

    cudaEventRecord(e0, 0);
    cudaStreamWaitEvent(s1, e0, 0);

    // s1: wconv (independent) runs under transpose
    wconv_kernel<<<1024, 256, 0, s1>>>(Wq, Wk, Wv, Wo);

    // s0: transpose -> assign -> mode
    transpose_kernel<<<1024, 256, TR_SMEM, 0>>>(x);
    cudaEventRecord(eT, 0);
    assign_kernel<<<1024, 256, AS_SMEM, 0>>>(protos);
    cudaEventRecord(eA, 0);
    mode_kernel<<<16, 256, 0, 0>>>(out);

    // s1: QKV GEMM (needs transpose) -> attention
    cudaStreamWaitEvent(s1, eT, 0);
    dim3 qkvgrid(BS_/64, 6);
    mma_gemm_kernel<<<qkvgrid, 256, GEMM_SMEM, s1>>>(pX2h, pX2l, pWth, pWtl,
                                                     bq, bk, bv, pQKVh, pQKVl);
    attn_mma_kernel<<<B_*H_, 128, 0, s1>>>();

    // s1: Wo + fused pooling (needs g_idx from assign)
    cudaStreamWaitEvent(s1, eA, 0);
    dim3 ogrid(BS_/64, 2);
    mma_gemm_wo_kernel<<<ogrid, 256, GEMM_SMEM, s1>>>(pATTh, pATTl,
                                                      pWth + 3*C_*C_, pWtl + 3*C_*C_,
                                                      bo, pX2);
    cudaEventRecord(eO, s1);

    cudaStreamWaitEvent(0, eO, 0);
    fc_kernel<<<256, 256, 0, 0>>>(fcb, out);
}

// round 11
// speedup vs baseline: 1.4760x; 1.4760x over previous
#include <cuda_runtime.h>
#include <cuda_bf16.h>
#include <math.h>
#include <float.h>
#include <stdint.h>

#define N_ 64
#define C_ 256
#define S_ 64
#define P_ 16
#define K_ 4
#define H_ 4
#define D_ 64
#define B_  (N_*P_)    /* 1024 */
#define BS_ (B_*S_)    /* 65536 */

// ---------------- scratch (static __device__, no allocations) ----------------
__device__ float g_X2 [BS_*C_];            // x2: (b, s, c) fp32
__device__ __nv_bfloat16 g_X2h[BS_*C_];    // bf16 hi of X2
__device__ __nv_bfloat16 g_X2l[BS_*C_];    // bf16 lo of X2
__device__ __nv_bfloat16 g_QKVh[3*BS_*C_]; // Q/K/V hi (mat-major)
__device__ __nv_bfloat16 g_QKVl[3*BS_*C_]; // Q/K/V lo
__device__ __nv_bfloat16 g_ATTh[BS_*C_];   // attention out (hi)
__device__ __nv_bfloat16 g_ATTl[BS_*C_];   // attention out (lo)
__device__ __nv_bfloat16 g_Wth[4*C_*C_];   // transposed weights hi: [mat][n][k]
__device__ __nv_bfloat16 g_Wtl[4*C_*C_];
__device__ int   g_idx[P_*N_*S_];
__device__ float g_clu[P_*N_*K_*C_];

// ---------------- helpers ----------------
__device__ __forceinline__ uint32_t smem_u32(const void* p) {
    uint32_t a;
    asm("{ .reg .u64 t; cvta.to.shared.u64 t, %1; cvt.u32.u64 %0, t; }" : "=r"(a) : "l"(p));
    return a;
}
__device__ __forceinline__ void ldsm4(uint32_t* r, uint32_t addr) {
    asm volatile("ldmatrix.sync.aligned.m8n8.x4.shared.b16 {%0,%1,%2,%3}, [%4];"
                 : "=r"(r[0]), "=r"(r[1]), "=r"(r[2]), "=r"(r[3]) : "r"(addr));
}
__device__ __forceinline__ void mma16816(float* d, const uint32_t* a, uint32_t b0, uint32_t b1) {
    asm volatile("mma.sync.aligned.m16n8k16.row.col.f32.bf16.bf16.f32 "
                 "{%0,%1,%2,%3}, {%4,%5,%6,%7}, {%8,%9}, {%0,%1,%2,%3};"
                 : "+f"(d[0]), "+f"(d[1]), "+f"(d[2]), "+f"(d[3])
                 : "r"(a[0]), "r"(a[1]), "r"(a[2]), "r"(a[3]), "r"(b0), "r"(b1));
}
__device__ __forceinline__ void cpasync16(uint32_t saddr, const void* g) {
    asm volatile("cp.async.cg.shared.global [%0], [%1], 16;" :: "r"(saddr), "l"(g) : "memory");
}
__device__ __forceinline__ void split_bf(float x, __nv_bfloat16& h, __nv_bfloat16& l) {
    h = __float2bfloat16_rn(x);
    l = __float2bfloat16_rn(x - __bfloat162float(h));
}
__device__ __forceinline__ void split2(float a, float b, uint32_t& h2, uint32_t& l2) {
    __nv_bfloat16 ha, la, hb, lb;
    split_bf(a, ha, la);
    split_bf(b, hb, lb);
    __nv_bfloat162 Hp; Hp.x = ha; Hp.y = hb;
    __nv_bfloat162 Lp; Lp.x = la; Lp.y = lb;
    h2 = *(uint32_t*)&Hp;
    l2 = *(uint32_t*)&Lp;
}

// ---------------- 1. transpose x(n,c,s,p) -> X2(n*16+p, s, c) + bf16 hi/lo ----------------
__global__ __launch_bounds__(256) void transpose_kernel(const float* __restrict__ x) {
    extern __shared__ float Ts[]; // [16][1025]
    int n  = blockIdx.x >> 4;
    int c0 = (blockIdx.x & 15) * 16;
    int t = threadIdx.x;
    const float* src = x + (size_t)(n*C_ + c0) * (S_*P_);
    for (int idx = t; idx < 16*1024; idx += 256) {
        int i = idx >> 10, sp = idx & 1023;
        Ts[i*1025 + sp] = src[i*1024 + sp];
    }
    __syncthreads();
    for (int idx = t; idx < 16*1024; idx += 256) {
        int sp = idx >> 4, i = idx & 15;
        int s = sp >> 4, p = sp & 15;
        size_t g = (size_t)((n*P_ + p)*S_ + s) * C_ + c0 + i;
        float v = Ts[i*1025 + sp];
        g_X2[g] = v;
        __nv_bfloat16 h, l; split_bf(v, h, l);
        g_X2h[g] = h;
        g_X2l[g] = l;
    }
}

// ---------------- 1b. weight transpose + hi/lo conversion ----------------
__global__ __launch_bounds__(256) void wconv_kernel(const float* __restrict__ Wq,
                                                    const float* __restrict__ Wk,
                                                    const float* __restrict__ Wv,
                                                    const float* __restrict__ Wo) {
    int g = blockIdx.x*256 + threadIdx.x;   // 0..262143
    int mat = g >> 16, rem = g & 65535;
    int n = rem >> 8, k = rem & 255;
    const float* W = (mat==0) ? Wq : (mat==1) ? Wk : (mat==2) ? Wv : Wo;
    float v = W[k*256 + n];
    __nv_bfloat16 h, l; split_bf(v, h, l);
    g_Wth[mat*65536 + n*256 + k] = h;
    g_Wtl[mat*65536 + n*256 + k] = l;
}

// ---------------- 2. instance-norm + cosine-sim argmax -> hard_idx ----------------
__global__ __launch_bounds__(256) void assign_kernel(const float* __restrict__ protos) {
    extern __shared__ float sm[];
    float* Xs   = sm;                // 64 x 260
    float* Ps   = Xs + 64*260;       // 4 x 256
    float* mu   = Ps + 4*256;        // 256
    float* rstd = mu + 256;          // 256
    float* rn   = rstd + 256;        // 4
    int p = blockIdx.x & 15;
    int n = blockIdx.x >> 4;
    int b = n*16 + p;
    int t = threadIdx.x;
    const float* xb = g_X2 + (size_t)b * S_ * C_;
    for (int idx = t; idx < S_*C_; idx += 256) {
        int s = idx >> 8, c = idx & 255;
        Xs[s*260 + c] = xb[idx];
    }
    for (int idx = t; idx < K_*C_; idx += 256)
        Ps[idx] = protos[p*K_*C_ + idx];
    __syncthreads();

    int w = t >> 5, lane = t & 31;
    if (w < 4) {
        float ss = 0.f;
        for (int c = lane; c < 256; c += 32) { float v = Ps[w*256 + c]; ss += v*v; }
        #pragma unroll
        for (int o = 16; o; o >>= 1) ss += __shfl_xor_sync(0xffffffffu, ss, o);
        if (lane == 0) rn[w] = rsqrtf(ss);
    }
    {
        int c = t;
        float s1 = 0.f;
        #pragma unroll 8
        for (int s = 0; s < 64; s++) s1 += Xs[s*260 + c];
        float m = s1 * (1.f/64.f);
        float s2 = 0.f;
        #pragma unroll 8
        for (int s = 0; s < 64; s++) { float d = Xs[s*260 + c] - m; s2 += d*d; }
        mu[c] = m;
        rstd[c] = rsqrtf(s2 * (1.f/64.f) + 1e-5f);
    }
    __syncthreads();

    int s = t >> 2, j = t & 3;
    float a0 = 0.f, a1 = 0.f, a2 = 0.f, a3 = 0.f;
    for (int cc = 0; cc < 64; cc++) {
        int c = cc*4 + j;
        float xv = (Xs[s*260 + c] - mu[c]) * rstd[c];
        a0 += xv * Ps[c];
        a1 += xv * Ps[256 + c];
        a2 += xv * Ps[512 + c];
        a3 += xv * Ps[768 + c];
    }
    #pragma unroll
    for (int o = 1; o <= 2; o <<= 1) {
        a0 += __shfl_xor_sync(0xffffffffu, a0, o);
        a1 += __shfl_xor_sync(0xffffffffu, a1, o);
        a2 += __shfl_xor_sync(0xffffffffu, a2, o);
        a3 += __shfl_xor_sync(0xffffffffu, a3, o);
    }
    if (j == 0) {
        float v0 = a0*rn[0], v1 = a1*rn[1], v2 = a2*rn[2], v3 = a3*rn[3];
        int best = 0; float bv = v0;
        if (v1 > bv) { bv = v1; best = 1; }
        if (v2 > bv) { bv = v2; best = 2; }
        if (v3 > bv) { bv = v3; best = 3; }
        g_idx[(p*N_ + n)*S_ + s] = best;
    }
}

// ---------------- 3. per-(n,s) mode over parts ----------------
__global__ __launch_bounds__(256) void mode_kernel(float* __restrict__ out) {
    int t = blockIdx.x*256 + threadIdx.x;   // n*64 + s
    if (t >= N_*S_) return;
    int n = t >> 6, s = t & 63;
    int c0=0,c1=0,c2=0,c3=0;
    #pragma unroll
    for (int p = 0; p < 16; p++) {
        int k = g_idx[(p*N_ + n)*S_ + s];
        c0 += (k==0); c1 += (k==1); c2 += (k==2); c3 += (k==3);
    }
    int best = 0, bc = c0;
    if (c1 > bc) { bc = c1; best = 1; }
    if (c2 > bc) { bc = c2; best = 2; }
    if (c3 > bc) { bc = c3; best = 3; }
    out[N_*C_*P_ + t] = (float)best;
}

// ---------------- 4. HMMA split-bf16 GEMM: CTA tile 64(M) x 128(N), 2 CTAs/SM ----------------
// 8 warps = 2(M) x 4(N), warp tile 32x32. K chunked by 64, 2-stage cp.async.
#define STG_AH 0
#define STG_AL 8192
#define STG_BH 16384
#define STG_BL 32768
#define STG_SZ 49152
#define GEMM_SMEM (2*STG_SZ)

__device__ __forceinline__ void gemm_mainloop(
    const __nv_bfloat16* __restrict__ Ah, const __nv_bfloat16* __restrict__ Al,
    const __nv_bfloat16* __restrict__ Bth, const __nv_bfloat16* __restrict__ Btl,
    char* smc, int m0, int n0, int tid, int wm, int wn, int lane,
    float acc[2][4][4])
{
    uint32_t sbase = smem_u32(smc);
    #pragma unroll
    for (int i = 0; i < 2; i++)
        #pragma unroll
        for (int j = 0; j < 4; j++)
            #pragma unroll
            for (int q = 0; q < 4; q++) acc[i][j][q] = 0.f;

    auto issue = [&](int kc, int stage) {
        int k0 = kc * 64;
        uint32_t st = sbase + stage*STG_SZ;
        #pragma unroll
        for (int it = 0; it < 2; it++) {
            int idx = tid + it*256;          // 0..511 -> A rows 0..63
            int row = idx >> 3, v = idx & 7;
            uint32_t off = (uint32_t)(row*128 + v*16);
            uint32_t sw = off ^ ((off >> 3) & 0x70);
            size_t ga = (size_t)(m0 + row)*256 + k0 + v*8;
            cpasync16(st + STG_AH + sw, Ah + ga);
            cpasync16(st + STG_AL + sw, Al + ga);
        }
        #pragma unroll
        for (int it = 0; it < 4; it++) {
            int idx = tid + it*256;          // 0..1023 -> B rows 0..127
            int row = idx >> 3, v = idx & 7;
            uint32_t off = (uint32_t)(row*128 + v*16);
            uint32_t sw = off ^ ((off >> 3) & 0x70);
            size_t gb = (size_t)(n0 + row)*256 + k0 + v*8;
            cpasync16(st + STG_BH + sw, Bth + gb);
            cpasync16(st + STG_BL + sw, Btl + gb);
        }
        asm volatile("cp.async.commit_group;" ::: "memory");
    };

    issue(0, 0);

    for (int kc = 0; kc < 4; kc++) {
        if (kc < 3) {
            issue(kc + 1, (kc + 1) & 1);
            asm volatile("cp.async.wait_group 1;" ::: "memory");
        } else {
            asm volatile("cp.async.wait_group 0;" ::: "memory");
        }
        __syncthreads();

        uint32_t st = sbase + (kc & 1)*STG_SZ;
        uint32_t sAh = st + STG_AH, sAl = st + STG_AL;
        uint32_t sBh = st + STG_BH, sBl = st + STG_BL;

        #pragma unroll
        for (int kk = 0; kk < 4; kk++) {
            uint32_t ah[2][4], al[2][4];
            #pragma unroll
            for (int mi = 0; mi < 2; mi++) {
                int r = wm*32 + mi*16 + (lane & 15);
                uint32_t off = (uint32_t)(r*128 + kk*32 + ((lane >> 4) & 1)*16);
                off ^= (off >> 3) & 0x70;
                ldsm4(ah[mi], sAh + off);
                ldsm4(al[mi], sAl + off);
            }
            uint32_t bh[2][4], bl[2][4];
            #pragma unroll
            for (int ni2 = 0; ni2 < 2; ni2++) {
                int r = wn*32 + ni2*16 + ((lane >> 4) & 1)*8 + (lane & 7);
                uint32_t off = (uint32_t)(r*128 + kk*32 + ((lane >> 3) & 1)*16);
                off ^= (off >> 3) & 0x70;
                ldsm4(bh[ni2], sBh + off);
                ldsm4(bl[ni2], sBl + off);
            }
            #pragma unroll
            for (int mi = 0; mi < 2; mi++) {
                #pragma unroll
                for (int ni = 0; ni < 4; ni++) {
                    int ni2 = ni >> 1, hf = (ni & 1)*2;
                    mma16816(acc[mi][ni], ah[mi], bh[ni2][hf], bh[ni2][hf+1]);
                    mma16816(acc[mi][ni], ah[mi], bl[ni2][hf], bl[ni2][hf+1]);
                    mma16816(acc[mi][ni], al[mi], bh[ni2][hf], bh[ni2][hf+1]);
                }
            }
        }
        __syncthreads();
    }
}

// QKV variant: bf16 hi/lo epilogue into g_QKVh/l, mat = n0>>8
__global__ __launch_bounds__(256, 2) void mma_gemm_kernel(
    const __nv_bfloat16* __restrict__ Ah, const __nv_bfloat16* __restrict__ Al,
    const __nv_bfloat16* __restrict__ Bth, const __nv_bfloat16* __restrict__ Btl,
    const float* __restrict__ b0p, const float* __restrict__ b1p, const float* __restrict__ b2p,
    __nv_bfloat16* __restrict__ outH, __nv_bfloat16* __restrict__ outL)
{
    extern __shared__ char smc[];
    int tid = threadIdx.x;
    int wid = tid >> 5, lane = tid & 31;
    int wm = wid >> 2, wn = wid & 3;
    int m0 = blockIdx.x * 64;
    int n0 = blockIdx.y * 128;

    float acc[2][4][4];
    gemm_mainloop(Ah, Al, Bth, Btl, smc, m0, n0, tid, wm, wn, lane, acc);

    int trow = lane >> 2, tcol = (lane & 3)*2;
    int mat = n0 >> 8;
    const float* bias = (mat == 0) ? b0p : (mat == 1) ? b1p : b2p;
    int clbase = (n0 & 255) + wn*32 + tcol;
    size_t moff = (size_t)mat * BS_ * C_;
    #pragma unroll
    for (int mi = 0; mi < 2; mi++) {
        #pragma unroll
        for (int ni = 0; ni < 4; ni++) {
            int cl = clbase + ni*8;
            size_t r0 = (size_t)(m0 + wm*32 + mi*16 + trow);
            size_t r1 = r0 + 8;
            float v0x = acc[mi][ni][0] + bias[cl];
            float v0y = acc[mi][ni][1] + bias[cl+1];
            float v1x = acc[mi][ni][2] + bias[cl];
            float v1y = acc[mi][ni][3] + bias[cl+1];
            uint32_t h2, l2;
            split2(v0x, v0y, h2, l2);
            *(uint32_t*)(outH + moff + r0*256 + cl) = h2;
            *(uint32_t*)(outL + moff + r0*256 + cl) = l2;
            split2(v1x, v1y, h2, l2);
            *(uint32_t*)(outH + moff + r1*256 + cl) = h2;
            *(uint32_t*)(outL + moff + r1*256 + cl) = l2;
        }
    }
}

// Wo variant: bias + residual, fused assignment-max pooling (one b per CTA)
#define TS_STRIDE 132
__global__ __launch_bounds__(256, 2) void mma_gemm_wo_kernel(
    const __nv_bfloat16* __restrict__ Ah, const __nv_bfloat16* __restrict__ Al,
    const __nv_bfloat16* __restrict__ Bth, const __nv_bfloat16* __restrict__ Btl,
    const float* __restrict__ bias, const float* __restrict__ res)
{
    extern __shared__ char smc[];
    int tid = threadIdx.x;
    int wid = tid >> 5, lane = tid & 31;
    int wm = wid >> 2, wn = wid & 3;
    int m0 = blockIdx.x * 64;
    int n0 = blockIdx.y * 128;

    float acc[2][4][4];
    gemm_mainloop(Ah, Al, Bth, Btl, smc, m0, n0, tid, wm, wn, lane, acc);

    float* TS = (float*)smc;                        // [64][TS_STRIDE]
    int* idxs = (int*)(smc + 64*TS_STRIDE*4);       // [64]
    int trow = lane >> 2, tcol = (lane & 3)*2;
    #pragma unroll
    for (int mi = 0; mi < 2; mi++) {
        #pragma unroll
        for (int ni = 0; ni < 4; ni++) {
            int lc = wn*32 + ni*8 + tcol;
            int lr0 = wm*32 + mi*16 + trow;
            int lr1 = lr0 + 8;
            int gc = n0 + lc;
            size_t r0 = (size_t)(m0 + lr0), r1 = (size_t)(m0 + lr1);
            float2 a0 = *(const float2*)(res + r0*256 + gc);
            float2 a1 = *(const float2*)(res + r1*256 + gc);
            TS[lr0*TS_STRIDE + lc]     = acc[mi][ni][0] + bias[gc]   + a0.x;
            TS[lr0*TS_STRIDE + lc + 1] = acc[mi][ni][1] + bias[gc+1] + a0.y;
            TS[lr1*TS_STRIDE + lc]     = acc[mi][ni][2] + bias[gc]   + a1.x;
            TS[lr1*TS_STRIDE + lc + 1] = acc[mi][ni][3] + bias[gc+1] + a1.y;
        }
    }
    int b = m0 >> 6;                 // one (n,p) per CTA
    int n = b >> 4, p = b & 15;
    if (tid < 64)
        idxs[tid] = g_idx[(p*N_ + n)*S_ + tid];
    __syncthreads();

    if (tid < 128) {
        int cl = tid;
        float m[4] = {-FLT_MAX, -FLT_MAX, -FLT_MAX, -FLT_MAX};
        int cnt[4] = {0, 0, 0, 0};
        #pragma unroll 8
        for (int s = 0; s < 64; s++) {
            float v = TS[s*TS_STRIDE + cl];
            int k = idxs[s];
            m[k] = fmaxf(m[k], v);
            cnt[k]++;
        }
        size_t cbase = ((size_t)(p*N_ + n)*4)*256 + n0 + cl;
        #pragma unroll
        for (int k = 0; k < 4; k++) {
            float r = (cnt[k] == 64) ? m[k] : fmaxf(m[k], 0.f);
            g_clu[cbase + (size_t)k*256] = r;
        }
    }
}

// ---------------- 5. HMMA causal attention: block per (b,h), 4 warps split q-rows ----------------
#define AQH 0
#define AQL 8192
#define AKH 16384
#define AKL 24576
#define AVH 32768
#define AVL 40960

__global__ __launch_bounds__(128) void attn_mma_kernel() {
    __shared__ __align__(16) char smem[49152];
    int bb = blockIdx.x >> 2, h = blockIdx.x & 3;
    int tid = threadIdx.x, lane = tid & 31, wq = tid >> 5;
    size_t gbase = (size_t)bb*64*256 + h*64;

    for (int i = tid; i < 2048; i += 128) {
        int arr = i >> 9, c = i & 511;
        int s = c >> 3, db = c & 7;
        const __nv_bfloat16* src = (arr & 1 ? g_QKVl : g_QKVh) + (size_t)(arr >> 1)*BS_*C_;
        uint32_t off = (uint32_t)(s*128 + db*16);
        off ^= (off >> 3) & 0x70;
        *(uint4*)(smem + arr*8192 + off) = *(const uint4*)(src + gbase + (size_t)s*256 + db*8);
    }
    for (int i = tid; i < 1024; i += 128) {
        int hl = i >> 9, c = i & 511;
        int s = c >> 3, db = c & 7;
        const __nv_bfloat16* src = (hl ? g_QKVl : g_QKVh) + (size_t)2*BS_*C_;
        uint4 pk = *(const uint4*)(src + gbase + (size_t)s*256 + db*8);
        const __nv_bfloat16* e = (const __nv_bfloat16*)&pk;
        #pragma unroll
        for (int j = 0; j < 8; j++) {
            uint32_t off = (uint32_t)((db*8 + j)*128 + s*2);
            off ^= (off >> 3) & 0x70;
            *(__nv_bfloat16*)(smem + AVH + hl*8192 + off) = e[j];
        }
    }
    __syncthreads();

    uint32_t sQh = smem_u32(smem + AQH), sQl = smem_u32(smem + AQL);
    uint32_t sKh = smem_u32(smem + AKH), sKl = smem_u32(smem + AKL);
    uint32_t sVh = smem_u32(smem + AVH), sVl = smem_u32(smem + AVL);

    float sc[8][4];
    #pragma unroll
    for (int i = 0; i < 8; i++)
        #pragma unroll
        for (int j = 0; j < 4; j++) sc[i][j] = 0.f;

    #pragma unroll
    for (int kk = 0; kk < 4; kk++) {
        uint32_t qh[4], ql[4];
        {
            int r = wq*16 + (lane & 15);
            uint32_t off = (uint32_t)(r*128 + kk*32 + ((lane >> 4) & 1)*16);
            off ^= (off >> 3) & 0x70;
            ldsm4(qh, sQh + off);
            ldsm4(ql, sQl + off);
        }
        #pragma unroll
        for (int ni2 = 0; ni2 < 4; ni2++) {
            uint32_t kh[4], kl[4];
            int r = ni2*16 + ((lane >> 4) & 1)*8 + (lane & 7);
            uint32_t off = (uint32_t)(r*128 + kk*32 + ((lane >> 3) & 1)*16);
            off ^= (off >> 3) & 0x70;
            ldsm4(kh, sKh + off);
            ldsm4(kl, sKl + off);
            mma16816(sc[2*ni2],   qh, kh[0], kh[1]);
            mma16816(sc[2*ni2],   qh, kl[0], kl[1]);
            mma16816(sc[2*ni2],   ql, kh[0], kh[1]);
            mma16816(sc[2*ni2+1], qh, kh[2], kh[3]);
            mma16816(sc[2*ni2+1], qh, kl[2], kl[3]);
            mma16816(sc[2*ni2+1], ql, kh[2], kh[3]);
        }
    }

    int trow = lane >> 2, tcolb = (lane & 3)*2;
    int q0 = wq*16 + trow, q1 = q0 + 8;
    float mx0 = -FLT_MAX, mx1 = -FLT_MAX;
    #pragma unroll
    for (int ni = 0; ni < 8; ni++) {
        int c0 = ni*8 + tcolb, c1 = c0 + 1;
        float v0 = (c0 <= q0) ? sc[ni][0]*0.125f : -FLT_MAX;
        float v1 = (c1 <= q0) ? sc[ni][1]*0.125f : -FLT_MAX;
        float v2 = (c0 <= q1) ? sc[ni][2]*0.125f : -FLT_MAX;
        float v3 = (c1 <= q1) ? sc[ni][3]*0.125f : -FLT_MAX;
        sc[ni][0] = v0; sc[ni][1] = v1; sc[ni][2] = v2; sc[ni][3] = v3;
        mx0 = fmaxf(mx0, fmaxf(v0, v1));
        mx1 = fmaxf(mx1, fmaxf(v2, v3));
    }
    mx0 = fmaxf(mx0, __shfl_xor_sync(0xffffffffu, mx0, 1));
    mx0 = fmaxf(mx0, __shfl_xor_sync(0xffffffffu, mx0, 2));
    mx1 = fmaxf(mx1, __shfl_xor_sync(0xffffffffu, mx1, 1));
    mx1 = fmaxf(mx1, __shfl_xor_sync(0xffffffffu, mx1, 2));
    float s0 = 0.f, s1 = 0.f;
    #pragma unroll
    for (int ni = 0; ni < 8; ni++) {
        float e0 = (sc[ni][0] > -FLT_MAX) ? expf(sc[ni][0] - mx0) : 0.f;
        float e1 = (sc[ni][1] > -FLT_MAX) ? expf(sc[ni][1] - mx0) : 0.f;
        float e2 = (sc[ni][2] > -FLT_MAX) ? expf(sc[ni][2] - mx1) : 0.f;
        float e3 = (sc[ni][3] > -FLT_MAX) ? expf(sc[ni][3] - mx1) : 0.f;
        sc[ni][0] = e0; sc[ni][1] = e1; sc[ni][2] = e2; sc[ni][3] = e3;
        s0 += e0 + e1;
        s1 += e2 + e3;
    }
    s0 += __shfl_xor_sync(0xffffffffu, s0, 1);
    s0 += __shfl_xor_sync(0xffffffffu, s0, 2);
    s1 += __shfl_xor_sync(0xffffffffu, s1, 1);
    s1 += __shfl_xor_sync(0xffffffffu, s1, 2);
    float i0 = 1.f/s0, i1 = 1.f/s1;
    #pragma unroll
    for (int ni = 0; ni < 8; ni++) {
        sc[ni][0] *= i0; sc[ni][1] *= i0;
        sc[ni][2] *= i1; sc[ni][3] *= i1;
    }

    float o[8][4];
    #pragma unroll
    for (int i = 0; i < 8; i++)
        #pragma unroll
        for (int j = 0; j < 4; j++) o[i][j] = 0.f;

    #pragma unroll
    for (int kt = 0; kt < 4; kt++) {
        uint32_t ph[4], pl[4];
        split2(sc[2*kt][0],   sc[2*kt][1],   ph[0], pl[0]);
        split2(sc[2*kt][2],   sc[2*kt][3],   ph[1], pl[1]);
        split2(sc[2*kt+1][0], sc[2*kt+1][1], ph[2], pl[2]);
        split2(sc[2*kt+1][2], sc[2*kt+1][3], ph[3], pl[3]);
        #pragma unroll
        for (int ni2 = 0; ni2 < 4; ni2++) {
            uint32_t vh[4], vl[4];
            int r = ni2*16 + ((lane >> 4) & 1)*8 + (lane & 7);
            uint32_t off = (uint32_t)(r*128 + kt*32 + ((lane >> 3) & 1)*16);
            off ^= (off >> 3) & 0x70;
            ldsm4(vh, sVh + off);
            ldsm4(vl, sVl + off);
            mma16816(o[2*ni2],   ph, vh[0], vh[1]);
            mma16816(o[2*ni2],   ph, vl[0], vl[1]);
            mma16816(o[2*ni2],   pl, vh[0], vh[1]);
            mma16816(o[2*ni2+1], ph, vh[2], vh[3]);
            mma16816(o[2*ni2+1], ph, vl[2], vl[3]);
            mma16816(o[2*ni2+1], pl, vh[2], vh[3]);
        }
    }

    size_t r0 = (size_t)bb*64 + wq*16 + trow;
    size_t r1 = r0 + 8;
    #pragma unroll
    for (int ni = 0; ni < 8; ni++) {
        int c = h*64 + ni*8 + tcolb;
        uint32_t h2, l2;
        split2(o[ni][0], o[ni][1], h2, l2);
        *(uint32_t*)(g_ATTh + r0*256 + c) = h2;
        *(uint32_t*)(g_ATTl + r0*256 + c) = l2;
        split2(o[ni][2], o[ni][3], h2, l2);
        *(uint32_t*)(g_ATTh + r1*256 + c) = h2;
        *(uint32_t*)(g_ATTl + r1*256 + c) = l2;
    }
}

// ---------------- 7. per-part FC: 256 blocks (p x 16 col-tiles) ----------------
__global__ __launch_bounds__(256) void fc_kernel(const float* __restrict__ fcb,
                                                 float* __restrict__ out) {
    __shared__ float As[32*68];
    __shared__ float Bs[32*17];
    int p  = blockIdx.x >> 4;
    int o0 = (blockIdx.x & 15) * 16;
    int t = threadIdx.x;
    int tm = t >> 4, tn = t & 15;
    const float* Ap = g_clu + (size_t)p*N_*1024;
    const float* Bp = fcb  + (size_t)p*1024*256;
    float acc[4] = {0.f, 0.f, 0.f, 0.f};

    for (int k0 = 0; k0 < 1024; k0 += 32) {
        #pragma unroll
        for (int i = 0; i < 8; i++) {
            int e = t + i*256;             // 0..2047
            int row = e >> 5, kk = e & 31;
            As[kk*68 + row] = Ap[(size_t)row*1024 + k0 + kk];
        }
        #pragma unroll
        for (int i = 0; i < 2; i++) {
            int e = t + i*256;             // 0..511
            int kk = e >> 4, oc = e & 15;
            Bs[kk*17 + oc] = Bp[(size_t)(k0 + kk)*256 + o0 + oc];
        }
        __syncthreads();
        #pragma unroll
        for (int kk = 0; kk < 32; kk++) {
            float4 a4 = *(const float4*)&As[kk*68 + tm*4];
            float b = Bs[kk*17 + tn];
            acc[0] += a4.x*b; acc[1] += a4.y*b; acc[2] += a4.z*b; acc[3] += a4.w*b;
        }
        __syncthreads();
    }
    #pragma unroll
    for (int i = 0; i < 4; i++) {
        int nrow = tm*4 + i;
        out[(size_t)nrow*C_*P_ + (o0 + tn)*P_ + p] = acc[i];
    }
}

// ---------------- launch ----------------
extern "C" void kernel_launch(void* const* d_in, const int* in_sizes, int n_in,
                              void* d_out, int out_size) {
    const float* x      = (const float*)d_in[0];
    const float* protos = (const float*)d_in[1];
    const float* Wq = (const float*)d_in[2];
    const float* bq = (const float*)d_in[3];
    const float* Wk = (const float*)d_in[4];
    const float* bk = (const float*)d_in[5];
    const float* Wv = (const float*)d_in[6];
    const float* bv = (const float*)d_in[7];
    const float* Wo = (const float*)d_in[8];
    const float* bo = (const float*)d_in[9];
    const float* fcb = (const float*)d_in[10];
    float* out = (float*)d_out;

    float *pX2;
    __nv_bfloat16 *pX2h, *pX2l, *pATTh, *pATTl, *pWth, *pWtl, *pQKVh, *pQKVl;
    cudaGetSymbolAddress((void**)&pX2,   g_X2);
    cudaGetSymbolAddress((void**)&pX2h,  g_X2h);
    cudaGetSymbolAddress((void**)&pX2l,  g_X2l);
    cudaGetSymbolAddress((void**)&pATTh, g_ATTh);
    cudaGetSymbolAddress((void**)&pATTl, g_ATTl);
    cudaGetSymbolAddress((void**)&pWth,  g_Wth);
    cudaGetSymbolAddress((void**)&pWtl,  g_Wtl);
    cudaGetSymbolAddress((void**)&pQKVh, g_QKVh);
    cudaGetSymbolAddress((void**)&pQKVl, g_QKVl);

    static cudaStream_t s1 = nullptr;
    static cudaEvent_t e0 = nullptr, eT = nullptr, eA = nullptr, eO = nullptr;
    if (!s1) {
        cudaStreamCreateWithFlags(&s1, cudaStreamNonBlocking);
        cudaEventCreateWithFlags(&e0, cudaEventDisableTiming);
        cudaEventCreateWithFlags(&eT, cudaEventDisableTiming);
        cudaEventCreateWithFlags(&eA, cudaEventDisableTiming);
        cudaEventCreateWithFlags(&eO, cudaEventDisableTiming);
    }

    const int TR_SMEM  = 16*1025*4;                          // 65600
    const int AS_SMEM  = (64*260 + 4*256 + 256 + 256 + 4)*4; // 72720
    cudaFuncSetAttribute(transpose_kernel,   cudaFuncAttributeMaxDynamicSharedMemorySize, TR_SMEM);
    cudaFuncSetAttribute(assign_kernel,      cudaFuncAttributeMaxDynamicSharedMemorySize, AS_SMEM);
    cudaFuncSetAttribute(mma_gemm_kernel,    cudaFuncAttributeMaxDynamicSharedMemorySize, GEMM_SMEM);
    cudaFuncSetAttribute(mma_gemm_wo_kernel, cudaFuncAttributeMaxDynamicSharedMemorySize, GEMM_SMEM);

    cudaEventRecord(e0, 0);
    cudaStreamWaitEvent(s1, e0, 0);

    // s1: wconv (independent) runs under transpose
    wconv_kernel<<<1024, 256, 0, s1>>>(Wq, Wk, Wv, Wo);

    // s0: transpose -> assign -> mode
    transpose_kernel<<<1024, 256, TR_SMEM, 0>>>(x);
    cudaEventRecord(eT, 0);
    assign_kernel<<<1024, 256, AS_SMEM, 0>>>(protos);
    cudaEventRecord(eA, 0);
    mode_kernel<<<16, 256, 0, 0>>>(out);

    // s1: QKV GEMM (needs transpose) -> attention
    cudaStreamWaitEvent(s1, eT, 0);
    dim3 qkvgrid(BS_/64, 6);
    mma_gemm_kernel<<<qkvgrid, 256, GEMM_SMEM, s1>>>(pX2h, pX2l, pWth, pWtl,
                                                     bq, bk, bv, pQKVh, pQKVl);
    attn_mma_kernel<<<B_*H_, 128, 0, s1>>>();

    // s1: Wo + fused pooling (needs g_idx from assign)
    cudaStreamWaitEvent(s1, eA, 0);
    dim3 ogrid(BS_/64, 2);
    mma_gemm_wo_kernel<<<ogrid, 256, GEMM_SMEM, s1>>>(pATTh, pATTl,
                                                      pWth + 3*C_*C_, pWtl + 3*C_*C_,
                                                      bo, pX2);
    cudaEventRecord(eO, s1);

    cudaStreamWaitEvent(0, eO, 0);
    fc_kernel<<<256, 256, 0, 0>>>(fcb, out);
}

// round 12
// speedup vs baseline: 1.5368x; 1.0412x over previous
#include <cuda_runtime.h>
#include <cuda_bf16.h>
#include <math.h>
#include <float.h>
#include <stdint.h>

#define N_ 64
#define C_ 256
#define S_ 64
#define P_ 16
#define K_ 4
#define H_ 4
#define D_ 64
#define B_  (N_*P_)    /* 1024 */
#define BS_ (B_*S_)    /* 65536 */

// ---------------- scratch (static __device__, no allocations) ----------------
__device__ float g_X2 [BS_*C_];            // x2: (b, s, c) fp32
__device__ __nv_bfloat16 g_X2h[BS_*C_];    // bf16 hi of X2
__device__ __nv_bfloat16 g_X2l[BS_*C_];    // bf16 lo of X2
__device__ __nv_bfloat16 g_QKVh[3*BS_*C_]; // Q/K/V hi (mat-major)
__device__ __nv_bfloat16 g_QKVl[3*BS_*C_]; // Q/K/V lo
__device__ __nv_bfloat16 g_ATTh[BS_*C_];   // attention out (hi)
__device__ __nv_bfloat16 g_ATTl[BS_*C_];   // attention out (lo)
__device__ __nv_bfloat16 g_Wth[4*C_*C_];   // transposed weights hi: [mat][n][k]
__device__ __nv_bfloat16 g_Wtl[4*C_*C_];
__device__ int   g_idx[P_*N_*S_];
__device__ float g_clu[P_*N_*K_*C_];

// ---------------- helpers ----------------
__device__ __forceinline__ uint32_t smem_u32(const void* p) {
    uint32_t a;
    asm("{ .reg .u64 t; cvta.to.shared.u64 t, %1; cvt.u32.u64 %0, t; }" : "=r"(a) : "l"(p));
    return a;
}
__device__ __forceinline__ void ldsm4(uint32_t* r, uint32_t addr) {
    asm volatile("ldmatrix.sync.aligned.m8n8.x4.shared.b16 {%0,%1,%2,%3}, [%4];"
                 : "=r"(r[0]), "=r"(r[1]), "=r"(r[2]), "=r"(r[3]) : "r"(addr));
}
__device__ __forceinline__ void mma16816(float* d, const uint32_t* a, uint32_t b0, uint32_t b1) {
    asm volatile("mma.sync.aligned.m16n8k16.row.col.f32.bf16.bf16.f32 "
                 "{%0,%1,%2,%3}, {%4,%5,%6,%7}, {%8,%9}, {%0,%1,%2,%3};"
                 : "+f"(d[0]), "+f"(d[1]), "+f"(d[2]), "+f"(d[3])
                 : "r"(a[0]), "r"(a[1]), "r"(a[2]), "r"(a[3]), "r"(b0), "r"(b1));
}
__device__ __forceinline__ void cpasync16(uint32_t saddr, const void* g) {
    asm volatile("cp.async.cg.shared.global [%0], [%1], 16;" :: "r"(saddr), "l"(g) : "memory");
}
__device__ __forceinline__ void split_bf(float x, __nv_bfloat16& h, __nv_bfloat16& l) {
    h = __float2bfloat16_rn(x);
    l = __float2bfloat16_rn(x - __bfloat162float(h));
}
__device__ __forceinline__ void split2(float a, float b, uint32_t& h2, uint32_t& l2) {
    __nv_bfloat16 ha, la, hb, lb;
    split_bf(a, ha, la);
    split_bf(b, hb, lb);
    __nv_bfloat162 Hp; Hp.x = ha; Hp.y = hb;
    __nv_bfloat162 Lp; Lp.x = la; Lp.y = lb;
    h2 = *(uint32_t*)&Hp;
    l2 = *(uint32_t*)&Lp;
}

// ---------------- 1. transpose x(n,c,s,p) -> X2(n*16+p, s, c) + bf16 hi/lo ----------------
__global__ __launch_bounds__(256) void transpose_kernel(const float* __restrict__ x) {
    extern __shared__ float Ts[]; // [16][1025]
    int n  = blockIdx.x >> 4;
    int c0 = (blockIdx.x & 15) * 16;
    int t = threadIdx.x;
    const float* src = x + (size_t)(n*C_ + c0) * (S_*P_);
    for (int idx = t; idx < 16*1024; idx += 256) {
        int i = idx >> 10, sp = idx & 1023;
        Ts[i*1025 + sp] = src[i*1024 + sp];
    }
    __syncthreads();
    for (int idx = t; idx < 16*1024; idx += 256) {
        int sp = idx >> 4, i = idx & 15;
        int s = sp >> 4, p = sp & 15;
        size_t g = (size_t)((n*P_ + p)*S_ + s) * C_ + c0 + i;
        float v = Ts[i*1025 + sp];
        g_X2[g] = v;
        __nv_bfloat16 h, l; split_bf(v, h, l);
        g_X2h[g] = h;
        g_X2l[g] = l;
    }
}

// ---------------- 1b. weight transpose + hi/lo conversion ----------------
__global__ __launch_bounds__(256) void wconv_kernel(const float* __restrict__ Wq,
                                                    const float* __restrict__ Wk,
                                                    const float* __restrict__ Wv,
                                                    const float* __restrict__ Wo) {
    int g = blockIdx.x*256 + threadIdx.x;   // 0..262143
    int mat = g >> 16, rem = g & 65535;
    int n = rem >> 8, k = rem & 255;
    const float* W = (mat==0) ? Wq : (mat==1) ? Wk : (mat==2) ? Wv : Wo;
    float v = W[k*256 + n];
    __nv_bfloat16 h, l; split_bf(v, h, l);
    g_Wth[mat*65536 + n*256 + k] = h;
    g_Wtl[mat*65536 + n*256 + k] = l;
}

// ---------------- 2. instance-norm + cosine-sim argmax -> hard_idx ----------------
__global__ __launch_bounds__(256) void assign_kernel(const float* __restrict__ protos) {
    extern __shared__ float sm[];
    float* Xs   = sm;                // 64 x 260
    float* Ps   = Xs + 64*260;       // 4 x 256
    float* mu   = Ps + 4*256;        // 256
    float* rstd = mu + 256;          // 256
    float* rn   = rstd + 256;        // 4
    int p = blockIdx.x & 15;
    int n = blockIdx.x >> 4;
    int b = n*16 + p;
    int t = threadIdx.x;
    const float* xb = g_X2 + (size_t)b * S_ * C_;
    for (int idx = t; idx < S_*C_; idx += 256) {
        int s = idx >> 8, c = idx & 255;
        Xs[s*260 + c] = xb[idx];
    }
    for (int idx = t; idx < K_*C_; idx += 256)
        Ps[idx] = protos[p*K_*C_ + idx];
    __syncthreads();

    int w = t >> 5, lane = t & 31;
    if (w < 4) {
        float ss = 0.f;
        for (int c = lane; c < 256; c += 32) { float v = Ps[w*256 + c]; ss += v*v; }
        #pragma unroll
        for (int o = 16; o; o >>= 1) ss += __shfl_xor_sync(0xffffffffu, ss, o);
        if (lane == 0) rn[w] = rsqrtf(ss);
    }
    {
        int c = t;
        float s1 = 0.f;
        #pragma unroll 8
        for (int s = 0; s < 64; s++) s1 += Xs[s*260 + c];
        float m = s1 * (1.f/64.f);
        float s2 = 0.f;
        #pragma unroll 8
        for (int s = 0; s < 64; s++) { float d = Xs[s*260 + c] - m; s2 += d*d; }
        mu[c] = m;
        rstd[c] = rsqrtf(s2 * (1.f/64.f) + 1e-5f);
    }
    __syncthreads();

    int s = t >> 2, j = t & 3;
    float a0 = 0.f, a1 = 0.f, a2 = 0.f, a3 = 0.f;
    for (int cc = 0; cc < 64; cc++) {
        int c = cc*4 + j;
        float xv = (Xs[s*260 + c] - mu[c]) * rstd[c];
        a0 += xv * Ps[c];
        a1 += xv * Ps[256 + c];
        a2 += xv * Ps[512 + c];
        a3 += xv * Ps[768 + c];
    }
    #pragma unroll
    for (int o = 1; o <= 2; o <<= 1) {
        a0 += __shfl_xor_sync(0xffffffffu, a0, o);
        a1 += __shfl_xor_sync(0xffffffffu, a1, o);
        a2 += __shfl_xor_sync(0xffffffffu, a2, o);
        a3 += __shfl_xor_sync(0xffffffffu, a3, o);
    }
    if (j == 0) {
        float v0 = a0*rn[0], v1 = a1*rn[1], v2 = a2*rn[2], v3 = a3*rn[3];
        int best = 0; float bv = v0;
        if (v1 > bv) { bv = v1; best = 1; }
        if (v2 > bv) { bv = v2; best = 2; }
        if (v3 > bv) { bv = v3; best = 3; }
        g_idx[(p*N_ + n)*S_ + s] = best;
    }
}

// ---------------- 3. per-(n,s) mode over parts ----------------
__global__ __launch_bounds__(256) void mode_kernel(float* __restrict__ out) {
    int t = blockIdx.x*256 + threadIdx.x;   // n*64 + s
    if (t >= N_*S_) return;
    int n = t >> 6, s = t & 63;
    int c0=0,c1=0,c2=0,c3=0;
    #pragma unroll
    for (int p = 0; p < 16; p++) {
        int k = g_idx[(p*N_ + n)*S_ + s];
        c0 += (k==0); c1 += (k==1); c2 += (k==2); c3 += (k==3);
    }
    int best = 0, bc = c0;
    if (c1 > bc) { bc = c1; best = 1; }
    if (c2 > bc) { bc = c2; best = 2; }
    if (c3 > bc) { bc = c3; best = 3; }
    out[N_*C_*P_ + t] = (float)best;
}

// ---------------- 4. HMMA split-bf16 GEMM: CTA tile 64(M) x 128(N), 2 CTAs/SM ----------------
// 8 warps = 2(M) x 4(N), warp tile 32x32. K chunked by 64, 2-stage cp.async.
#define STG_AH 0
#define STG_AL 8192
#define STG_BH 16384
#define STG_BL 32768
#define STG_SZ 49152
#define GEMM_SMEM (2*STG_SZ)

__device__ __forceinline__ void gemm_mainloop(
    const __nv_bfloat16* __restrict__ Ah, const __nv_bfloat16* __restrict__ Al,
    const __nv_bfloat16* __restrict__ Bth, const __nv_bfloat16* __restrict__ Btl,
    char* smc, int m0, int n0, int tid, int wm, int wn, int lane,
    float acc[2][4][4])
{
    uint32_t sbase = smem_u32(smc);
    #pragma unroll
    for (int i = 0; i < 2; i++)
        #pragma unroll
        for (int j = 0; j < 4; j++)
            #pragma unroll
            for (int q = 0; q < 4; q++) acc[i][j][q] = 0.f;

    auto issue = [&](int kc, int stage) {
        int k0 = kc * 64;
        uint32_t st = sbase + stage*STG_SZ;
        #pragma unroll
        for (int it = 0; it < 2; it++) {
            int idx = tid + it*256;          // 0..511 -> A rows 0..63
            int row = idx >> 3, v = idx & 7;
            uint32_t off = (uint32_t)(row*128 + v*16);
            uint32_t sw = off ^ ((off >> 3) & 0x70);
            size_t ga = (size_t)(m0 + row)*256 + k0 + v*8;
            cpasync16(st + STG_AH + sw, Ah + ga);
            cpasync16(st + STG_AL + sw, Al + ga);
        }
        #pragma unroll
        for (int it = 0; it < 4; it++) {
            int idx = tid + it*256;          // 0..1023 -> B rows 0..127
            int row = idx >> 3, v = idx & 7;
            uint32_t off = (uint32_t)(row*128 + v*16);
            uint32_t sw = off ^ ((off >> 3) & 0x70);
            size_t gb = (size_t)(n0 + row)*256 + k0 + v*8;
            cpasync16(st + STG_BH + sw, Bth + gb);
            cpasync16(st + STG_BL + sw, Btl + gb);
        }
        asm volatile("cp.async.commit_group;" ::: "memory");
    };

    issue(0, 0);

    for (int kc = 0; kc < 4; kc++) {
        if (kc < 3) {
            issue(kc + 1, (kc + 1) & 1);
            asm volatile("cp.async.wait_group 1;" ::: "memory");
        } else {
            asm volatile("cp.async.wait_group 0;" ::: "memory");
        }
        __syncthreads();

        uint32_t st = sbase + (kc & 1)*STG_SZ;
        uint32_t sAh = st + STG_AH, sAl = st + STG_AL;
        uint32_t sBh = st + STG_BH, sBl = st + STG_BL;

        #pragma unroll
        for (int kk = 0; kk < 4; kk++) {
            uint32_t ah[2][4], al[2][4];
            #pragma unroll
            for (int mi = 0; mi < 2; mi++) {
                int r = wm*32 + mi*16 + (lane & 15);
                uint32_t off = (uint32_t)(r*128 + kk*32 + ((lane >> 4) & 1)*16);
                off ^= (off >> 3) & 0x70;
                ldsm4(ah[mi], sAh + off);
                ldsm4(al[mi], sAl + off);
            }
            uint32_t bh[2][4], bl[2][4];
            #pragma unroll
            for (int ni2 = 0; ni2 < 2; ni2++) {
                int r = wn*32 + ni2*16 + ((lane >> 4) & 1)*8 + (lane & 7);
                uint32_t off = (uint32_t)(r*128 + kk*32 + ((lane >> 3) & 1)*16);
                off ^= (off >> 3) & 0x70;
                ldsm4(bh[ni2], sBh + off);
                ldsm4(bl[ni2], sBl + off);
            }
            #pragma unroll
            for (int mi = 0; mi < 2; mi++) {
                #pragma unroll
                for (int ni = 0; ni < 4; ni++) {
                    int ni2 = ni >> 1, hf = (ni & 1)*2;
                    mma16816(acc[mi][ni], ah[mi], bh[ni2][hf], bh[ni2][hf+1]);
                    mma16816(acc[mi][ni], ah[mi], bl[ni2][hf], bl[ni2][hf+1]);
                    mma16816(acc[mi][ni], al[mi], bh[ni2][hf], bh[ni2][hf+1]);
                }
            }
        }
        __syncthreads();
    }
}

// QKV variant: bf16 hi/lo epilogue into g_QKVh/l, mat = n0>>8
__global__ __launch_bounds__(256, 2) void mma_gemm_kernel(
    const __nv_bfloat16* __restrict__ Ah, const __nv_bfloat16* __restrict__ Al,
    const __nv_bfloat16* __restrict__ Bth, const __nv_bfloat16* __restrict__ Btl,
    const float* __restrict__ b0p, const float* __restrict__ b1p, const float* __restrict__ b2p,
    __nv_bfloat16* __restrict__ outH, __nv_bfloat16* __restrict__ outL)
{
    extern __shared__ char smc[];
    int tid = threadIdx.x;
    int wid = tid >> 5, lane = tid & 31;
    int wm = wid >> 2, wn = wid & 3;
    int m0 = blockIdx.x * 64;
    int n0 = blockIdx.y * 128;

    float acc[2][4][4];
    gemm_mainloop(Ah, Al, Bth, Btl, smc, m0, n0, tid, wm, wn, lane, acc);

    int trow = lane >> 2, tcol = (lane & 3)*2;
    int mat = n0 >> 8;
    const float* bias = (mat == 0) ? b0p : (mat == 1) ? b1p : b2p;
    int clbase = (n0 & 255) + wn*32 + tcol;
    size_t moff = (size_t)mat * BS_ * C_;
    #pragma unroll
    for (int mi = 0; mi < 2; mi++) {
        #pragma unroll
        for (int ni = 0; ni < 4; ni++) {
            int cl = clbase + ni*8;
            size_t r0 = (size_t)(m0 + wm*32 + mi*16 + trow);
            size_t r1 = r0 + 8;
            float v0x = acc[mi][ni][0] + bias[cl];
            float v0y = acc[mi][ni][1] + bias[cl+1];
            float v1x = acc[mi][ni][2] + bias[cl];
            float v1y = acc[mi][ni][3] + bias[cl+1];
            uint32_t h2, l2;
            split2(v0x, v0y, h2, l2);
            *(uint32_t*)(outH + moff + r0*256 + cl) = h2;
            *(uint32_t*)(outL + moff + r0*256 + cl) = l2;
            split2(v1x, v1y, h2, l2);
            *(uint32_t*)(outH + moff + r1*256 + cl) = h2;
            *(uint32_t*)(outL + moff + r1*256 + cl) = l2;
        }
    }
}

// Wo variant: bias + residual, fused assignment-max pooling (one b per CTA)
#define TS_STRIDE 132
__global__ __launch_bounds__(256, 2) void mma_gemm_wo_kernel(
    const __nv_bfloat16* __restrict__ Ah, const __nv_bfloat16* __restrict__ Al,
    const __nv_bfloat16* __restrict__ Bth, const __nv_bfloat16* __restrict__ Btl,
    const float* __restrict__ bias, const float* __restrict__ res)
{
    extern __shared__ char smc[];
    int tid = threadIdx.x;
    int wid = tid >> 5, lane = tid & 31;
    int wm = wid >> 2, wn = wid & 3;
    int m0 = blockIdx.x * 64;
    int n0 = blockIdx.y * 128;

    float acc[2][4][4];
    gemm_mainloop(Ah, Al, Bth, Btl, smc, m0, n0, tid, wm, wn, lane, acc);

    float* TS = (float*)smc;                        // [64][TS_STRIDE]
    int* idxs = (int*)(smc + 64*TS_STRIDE*4);       // [64]
    int trow = lane >> 2, tcol = (lane & 3)*2;
    #pragma unroll
    for (int mi = 0; mi < 2; mi++) {
        #pragma unroll
        for (int ni = 0; ni < 4; ni++) {
            int lc = wn*32 + ni*8 + tcol;
            int lr0 = wm*32 + mi*16 + trow;
            int lr1 = lr0 + 8;
            int gc = n0 + lc;
            size_t r0 = (size_t)(m0 + lr0), r1 = (size_t)(m0 + lr1);
            float2 a0 = *(const float2*)(res + r0*256 + gc);
            float2 a1 = *(const float2*)(res + r1*256 + gc);
            TS[lr0*TS_STRIDE + lc]     = acc[mi][ni][0] + bias[gc]   + a0.x;
            TS[lr0*TS_STRIDE + lc + 1] = acc[mi][ni][1] + bias[gc+1] + a0.y;
            TS[lr1*TS_STRIDE + lc]     = acc[mi][ni][2] + bias[gc]   + a1.x;
            TS[lr1*TS_STRIDE + lc + 1] = acc[mi][ni][3] + bias[gc+1] + a1.y;
        }
    }
    int b = m0 >> 6;                 // one (n,p) per CTA
    int n = b >> 4, p = b & 15;
    if (tid < 64)
        idxs[tid] = g_idx[(p*N_ + n)*S_ + tid];
    __syncthreads();

    if (tid < 128) {
        int cl = tid;
        float m[4] = {-FLT_MAX, -FLT_MAX, -FLT_MAX, -FLT_MAX};
        int cnt[4] = {0, 0, 0, 0};
        #pragma unroll 8
        for (int s = 0; s < 64; s++) {
            float v = TS[s*TS_STRIDE + cl];
            int k = idxs[s];
            m[k] = fmaxf(m[k], v);
            cnt[k]++;
        }
        size_t cbase = ((size_t)(p*N_ + n)*4)*256 + n0 + cl;
        #pragma unroll
        for (int k = 0; k < 4; k++) {
            float r = (cnt[k] == 64) ? m[k] : fmaxf(m[k], 0.f);
            g_clu[cbase + (size_t)k*256] = r;
        }
    }
}

// ---------------- 5. HMMA causal attention: block per (b,h), 4 warps split q-rows ----------------
#define AQH 0
#define AQL 8192
#define AKH 16384
#define AKL 24576
#define AVH 32768
#define AVL 40960

__global__ __launch_bounds__(128) void attn_mma_kernel() {
    __shared__ __align__(16) char smem[49152];
    int bb = blockIdx.x >> 2, h = blockIdx.x & 3;
    int tid = threadIdx.x, lane = tid & 31, wq = tid >> 5;
    size_t gbase = (size_t)bb*64*256 + h*64;

    for (int i = tid; i < 2048; i += 128) {
        int arr = i >> 9, c = i & 511;
        int s = c >> 3, db = c & 7;
        const __nv_bfloat16* src = (arr & 1 ? g_QKVl : g_QKVh) + (size_t)(arr >> 1)*BS_*C_;
        uint32_t off = (uint32_t)(s*128 + db*16);
        off ^= (off >> 3) & 0x70;
        *(uint4*)(smem + arr*8192 + off) = *(const uint4*)(src + gbase + (size_t)s*256 + db*8);
    }
    // V transposed: Vt[d][s]; j-iteration rotated per thread (j = (jj+db)&7) so the
    // 8 threads sharing a column hit 8 distinct banks instead of 1 (same bytes, same
    // addresses, different order -> bit-identical result, ~8x fewer ST conflicts).
    for (int i = tid; i < 1024; i += 128) {
        int hl = i >> 9, c = i & 511;
        int s = c >> 3, db = c & 7;
        const __nv_bfloat16* src = (hl ? g_QKVl : g_QKVh) + (size_t)2*BS_*C_;
        uint4 pk = *(const uint4*)(src + gbase + (size_t)s*256 + db*8);
        const __nv_bfloat16* e = (const __nv_bfloat16*)&pk;
        #pragma unroll
        for (int jj = 0; jj < 8; jj++) {
            int j = (jj + db) & 7;
            uint32_t off = (uint32_t)((db*8 + j)*128 + s*2);
            off ^= (off >> 3) & 0x70;
            *(__nv_bfloat16*)(smem + AVH + hl*8192 + off) = e[j];
        }
    }
    __syncthreads();

    uint32_t sQh = smem_u32(smem + AQH), sQl = smem_u32(smem + AQL);
    uint32_t sKh = smem_u32(smem + AKH), sKl = smem_u32(smem + AKL);
    uint32_t sVh = smem_u32(smem + AVH), sVl = smem_u32(smem + AVL);

    float sc[8][4];
    #pragma unroll
    for (int i = 0; i < 8; i++)
        #pragma unroll
        for (int j = 0; j < 4; j++) sc[i][j] = 0.f;

    #pragma unroll
    for (int kk = 0; kk < 4; kk++) {
        uint32_t qh[4], ql[4];
        {
            int r = wq*16 + (lane & 15);
            uint32_t off = (uint32_t)(r*128 + kk*32 + ((lane >> 4) & 1)*16);
            off ^= (off >> 3) & 0x70;
            ldsm4(qh, sQh + off);
            ldsm4(ql, sQl + off);
        }
        #pragma unroll
        for (int ni2 = 0; ni2 < 4; ni2++) {
            uint32_t kh[4], kl[4];
            int r = ni2*16 + ((lane >> 4) & 1)*8 + (lane & 7);
            uint32_t off = (uint32_t)(r*128 + kk*32 + ((lane >> 3) & 1)*16);
            off ^= (off >> 3) & 0x70;
            ldsm4(kh, sKh + off);
            ldsm4(kl, sKl + off);
            mma16816(sc[2*ni2],   qh, kh[0], kh[1]);
            mma16816(sc[2*ni2],   qh, kl[0], kl[1]);
            mma16816(sc[2*ni2],   ql, kh[0], kh[1]);
            mma16816(sc[2*ni2+1], qh, kh[2], kh[3]);
            mma16816(sc[2*ni2+1], qh, kl[2], kl[3]);
            mma16816(sc[2*ni2+1], ql, kh[2], kh[3]);
        }
    }

    int trow = lane >> 2, tcolb = (lane & 3)*2;
    int q0 = wq*16 + trow, q1 = q0 + 8;
    float mx0 = -FLT_MAX, mx1 = -FLT_MAX;
    #pragma unroll
    for (int ni = 0; ni < 8; ni++) {
        int c0 = ni*8 + tcolb, c1 = c0 + 1;
        float v0 = (c0 <= q0) ? sc[ni][0]*0.125f : -FLT_MAX;
        float v1 = (c1 <= q0) ? sc[ni][1]*0.125f : -FLT_MAX;
        float v2 = (c0 <= q1) ? sc[ni][2]*0.125f : -FLT_MAX;
        float v3 = (c1 <= q1) ? sc[ni][3]*0.125f : -FLT_MAX;
        sc[ni][0] = v0; sc[ni][1] = v1; sc[ni][2] = v2; sc[ni][3] = v3;
        mx0 = fmaxf(mx0, fmaxf(v0, v1));
        mx1 = fmaxf(mx1, fmaxf(v2, v3));
    }
    mx0 = fmaxf(mx0, __shfl_xor_sync(0xffffffffu, mx0, 1));
    mx0 = fmaxf(mx0, __shfl_xor_sync(0xffffffffu, mx0, 2));
    mx1 = fmaxf(mx1, __shfl_xor_sync(0xffffffffu, mx1, 1));
    mx1 = fmaxf(mx1, __shfl_xor_sync(0xffffffffu, mx1, 2));
    float s0 = 0.f, s1 = 0.f;
    #pragma unroll
    for (int ni = 0; ni < 8; ni++) {
        float e0 = (sc[ni][0] > -FLT_MAX) ? expf(sc[ni][0] - mx0) : 0.f;
        float e1 = (sc[ni][1] > -FLT_MAX) ? expf(sc[ni][1] - mx0) : 0.f;
        float e2 = (sc[ni][2] > -FLT_MAX) ? expf(sc[ni][2] - mx1) : 0.f;
        float e3 = (sc[ni][3] > -FLT_MAX) ? expf(sc[ni][3] - mx1) : 0.f;
        sc[ni][0] = e0; sc[ni][1] = e1; sc[ni][2] = e2; sc[ni][3] = e3;
        s0 += e0 + e1;
        s1 += e2 + e3;
    }
    s0 += __shfl_xor_sync(0xffffffffu, s0, 1);
    s0 += __shfl_xor_sync(0xffffffffu, s0, 2);
    s1 += __shfl_xor_sync(0xffffffffu, s1, 1);
    s1 += __shfl_xor_sync(0xffffffffu, s1, 2);
    float i0 = 1.f/s0, i1 = 1.f/s1;
    #pragma unroll
    for (int ni = 0; ni < 8; ni++) {
        sc[ni][0] *= i0; sc[ni][1] *= i0;
        sc[ni][2] *= i1; sc[ni][3] *= i1;
    }

    float o[8][4];
    #pragma unroll
    for (int i = 0; i < 8; i++)
        #pragma unroll
        for (int j = 0; j < 4; j++) o[i][j] = 0.f;

    #pragma unroll
    for (int kt = 0; kt < 4; kt++) {
        uint32_t ph[4], pl[4];
        split2(sc[2*kt][0],   sc[2*kt][1],   ph[0], pl[0]);
        split2(sc[2*kt][2],   sc[2*kt][3],   ph[1], pl[1]);
        split2(sc[2*kt+1][0], sc[2*kt+1][1], ph[2], pl[2]);
        split2(sc[2*kt+1][2], sc[2*kt+1][3], ph[3], pl[3]);
        #pragma unroll
        for (int ni2 = 0; ni2 < 4; ni2++) {
            uint32_t vh[4], vl[4];
            int r = ni2*16 + ((lane >> 4) & 1)*8 + (lane & 7);
            uint32_t off = (uint32_t)(r*128 + kt*32 + ((lane >> 3) & 1)*16);
            off ^= (off >> 3) & 0x70;
            ldsm4(vh, sVh + off);
            ldsm4(vl, sVl + off);
            mma16816(o[2*ni2],   ph, vh[0], vh[1]);
            mma16816(o[2*ni2],   ph, vl[0], vl[1]);
            mma16816(o[2*ni2],   pl, vh[0], vh[1]);
            mma16816(o[2*ni2+1], ph, vh[2], vh[3]);
            mma16816(o[2*ni2+1], ph, vl[2], vl[3]);
            mma16816(o[2*ni2+1], pl, vh[2], vh[3]);
        }
    }

    size_t r0 = (size_t)bb*64 + wq*16 + trow;
    size_t r1 = r0 + 8;
    #pragma unroll
    for (int ni = 0; ni < 8; ni++) {
        int c = h*64 + ni*8 + tcolb;
        uint32_t h2, l2;
        split2(o[ni][0], o[ni][1], h2, l2);
        *(uint32_t*)(g_ATTh + r0*256 + c) = h2;
        *(uint32_t*)(g_ATTl + r0*256 + c) = l2;
        split2(o[ni][2], o[ni][3], h2, l2);
        *(uint32_t*)(g_ATTh + r1*256 + c) = h2;
        *(uint32_t*)(g_ATTl + r1*256 + c) = l2;
    }
}

// ---------------- 7. per-part FC: 256 blocks (p x 16 col-tiles) ----------------
__global__ __launch_bounds__(256) void fc_kernel(const float* __restrict__ fcb,
                                                 float* __restrict__ out) {
    __shared__ float As[32*68];
    __shared__ float Bs[32*17];
    int p  = blockIdx.x >> 4;
    int o0 = (blockIdx.x & 15) * 16;
    int t = threadIdx.x;
    int tm = t >> 4, tn = t & 15;
    const float* Ap = g_clu + (size_t)p*N_*1024;
    const float* Bp = fcb  + (size_t)p*1024*256;
    float acc[4] = {0.f, 0.f, 0.f, 0.f};

    for (int k0 = 0; k0 < 1024; k0 += 32) {
        #pragma unroll
        for (int i = 0; i < 8; i++) {
            int e = t + i*256;             // 0..2047
            int row = e >> 5, kk = e & 31;
            As[kk*68 + row] = Ap[(size_t)row*1024 + k0 + kk];
        }
        #pragma unroll
        for (int i = 0; i < 2; i++) {
            int e = t + i*256;             // 0..511
            int kk = e >> 4, oc = e & 15;
            Bs[kk*17 + oc] = Bp[(size_t)(k0 + kk)*256 + o0 + oc];
        }
        __syncthreads();
        #pragma unroll
        for (int kk = 0; kk < 32; kk++) {
            float4 a4 = *(const float4*)&As[kk*68 + tm*4];
            float b = Bs[kk*17 + tn];
            acc[0] += a4.x*b; acc[1] += a4.y*b; acc[2] += a4.z*b; acc[3] += a4.w*b;
        }
        __syncthreads();
    }
    #pragma unroll
    for (int i = 0; i < 4; i++) {
        int nrow = tm*4 + i;
        out[(size_t)nrow*C_*P_ + (o0 + tn)*P_ + p] = acc[i];
    }
}

// ---------------- launch ----------------
extern "C" void kernel_launch(void* const* d_in, const int* in_sizes, int n_in,
                              void* d_out, int out_size) {
    const float* x      = (const float*)d_in[0];
    const float* protos = (const float*)d_in[1];
    const float* Wq = (const float*)d_in[2];
    const float* bq = (const float*)d_in[3];
    const float* Wk = (const float*)d_in[4];
    const float* bk = (const float*)d_in[5];
    const float* Wv = (const float*)d_in[6];
    const float* bv = (const float*)d_in[7];
    const float* Wo = (const float*)d_in[8];
    const float* bo = (const float*)d_in[9];
    const float* fcb = (const float*)d_in[10];
    float* out = (float*)d_out;

    float *pX2;
    __nv_bfloat16 *pX2h, *pX2l, *pATTh, *pATTl, *pWth, *pWtl, *pQKVh, *pQKVl;
    cudaGetSymbolAddress((void**)&pX2,   g_X2);
    cudaGetSymbolAddress((void**)&pX2h,  g_X2h);
    cudaGetSymbolAddress((void**)&pX2l,  g_X2l);
    cudaGetSymbolAddress((void**)&pATTh, g_ATTh);
    cudaGetSymbolAddress((void**)&pATTl, g_ATTl);
    cudaGetSymbolAddress((void**)&pWth,  g_Wth);
    cudaGetSymbolAddress((void**)&pWtl,  g_Wtl);
    cudaGetSymbolAddress((void**)&pQKVh, g_QKVh);
    cudaGetSymbolAddress((void**)&pQKVl, g_QKVl);

    static cudaStream_t s1 = nullptr;
    static cudaEvent_t e0 = nullptr, eT = nullptr, eA = nullptr, eO = nullptr;
    if (!s1) {
        cudaStreamCreateWithFlags(&s1, cudaStreamNonBlocking);
        cudaEventCreateWithFlags(&e0, cudaEventDisableTiming);
        cudaEventCreateWithFlags(&eT, cudaEventDisableTiming);
        cudaEventCreateWithFlags(&eA, cudaEventDisableTiming);
        cudaEventCreateWithFlags(&eO, cudaEventDisableTiming);
    }

    const int TR_SMEM  = 16*1025*4;                          // 65600
    const int AS_SMEM  = (64*260 + 4*256 + 256 + 256 + 4)*4; // 72720
    cudaFuncSetAttribute(transpose_kernel,   cudaFuncAttributeMaxDynamicSharedMemorySize, TR_SMEM);
    cudaFuncSetAttribute(assign_kernel,      cudaFuncAttributeMaxDynamicSharedMemorySize, AS_SMEM);
    cudaFuncSetAttribute(mma_gemm_kernel,    cudaFuncAttributeMaxDynamicSharedMemorySize, GEMM_SMEM);
    cudaFuncSetAttribute(mma_gemm_wo_kernel, cudaFuncAttributeMaxDynamicSharedMemorySize, GEMM_SMEM);

    cudaEventRecord(e0, 0);
    cudaStreamWaitEvent(s1, e0, 0);

    // submission order chosen so the QKV GEMM is the 4th launch (ncu -s window).
    // 1: wconv (s1) — runs under transpose
    wconv_kernel<<<1024, 256, 0, s1>>>(Wq, Wk, Wv, Wo);

    // 2: transpose (s0), 3: assign (s0)
    transpose_kernel<<<1024, 256, TR_SMEM, 0>>>(x);
    cudaEventRecord(eT, 0);
    assign_kernel<<<1024, 256, AS_SMEM, 0>>>(protos);
    cudaEventRecord(eA, 0);

    // 4: QKV GEMM (s1, waits transpose), 5: attention (s1)
    cudaStreamWaitEvent(s1, eT, 0);
    dim3 qkvgrid(BS_/64, 6);
    mma_gemm_kernel<<<qkvgrid, 256, GEMM_SMEM, s1>>>(pX2h, pX2l, pWth, pWtl,
                                                     bq, bk, bv, pQKVh, pQKVl);
    attn_mma_kernel<<<B_*H_, 128, 0, s1>>>();

    // 6: mode (s0, after assign in-stream)
    mode_kernel<<<16, 256, 0, 0>>>(out);

    // 7: Wo + fused pooling (s1, needs g_idx from assign)
    cudaStreamWaitEvent(s1, eA, 0);
    dim3 ogrid(BS_/64, 2);
    mma_gemm_wo_kernel<<<ogrid, 256, GEMM_SMEM, s1>>>(pATTh, pATTl,
                                                      pWth + 3*C_*C_, pWtl + 3*C_*C_,
                                                      bo, pX2);
    cudaEventRecord(eO, s1);

    // 8: fc (s0, joins s1)
    cudaStreamWaitEvent(0, eO, 0);
    fc_kernel<<<256, 256, 0, 0>>>(fcb, out);
}

// round 13
// speedup vs baseline: 2.5139x; 1.6358x over previous
#include <cuda_runtime.h>
#include <cuda_fp16.h>
#include <math.h>
#include <float.h>
#include <stdint.h>

#define N_ 64
#define C_ 256
#define S_ 64
#define P_ 16
#define K_ 4
#define H_ 4
#define D_ 64
#define B_  (N_*P_)    /* 1024 */
#define BS_ (B_*S_)    /* 65536 */

// ---------------- scratch (static __device__, no allocations) ----------------
__device__ float  g_X2 [BS_*C_];        // x2: (b, s, c) fp32 (assign + residual)
__device__ __half g_X2f[BS_*C_];        // fp16 of X2
__device__ __half g_QKV[3*BS_*C_];      // Q/K/V fp16 (mat-major)
__device__ __half g_ATT[BS_*C_];        // attention out fp16
__device__ __half g_Wtf[4*C_*C_];       // transposed weights fp16: [mat][n][k]
__device__ int    g_idx[P_*N_*S_];
__device__ float  g_clu[P_*N_*K_*C_];

// ---------------- helpers ----------------
__device__ __forceinline__ uint32_t smem_u32(const void* p) {
    uint32_t a;
    asm("{ .reg .u64 t; cvta.to.shared.u64 t, %1; cvt.u32.u64 %0, t; }" : "=r"(a) : "l"(p));
    return a;
}
__device__ __forceinline__ void ldsm4(uint32_t* r, uint32_t addr) {
    asm volatile("ldmatrix.sync.aligned.m8n8.x4.shared.b16 {%0,%1,%2,%3}, [%4];"
                 : "=r"(r[0]), "=r"(r[1]), "=r"(r[2]), "=r"(r[3]) : "r"(addr));
}
__device__ __forceinline__ void mma16816(float* d, const uint32_t* a, uint32_t b0, uint32_t b1) {
    asm volatile("mma.sync.aligned.m16n8k16.row.col.f32.f16.f16.f32 "
                 "{%0,%1,%2,%3}, {%4,%5,%6,%7}, {%8,%9}, {%0,%1,%2,%3};"
                 : "+f"(d[0]), "+f"(d[1]), "+f"(d[2]), "+f"(d[3])
                 : "r"(a[0]), "r"(a[1]), "r"(a[2]), "r"(a[3]), "r"(b0), "r"(b1));
}
__device__ __forceinline__ void cpasync16(uint32_t saddr, const void* g) {
    asm volatile("cp.async.cg.shared.global [%0], [%1], 16;" :: "r"(saddr), "l"(g) : "memory");
}
__device__ __forceinline__ uint32_t packh2(float a, float b) {
    __half2 h = __floats2half2_rn(a, b);   // .x = a (low half), .y = b
    return *(uint32_t*)&h;
}

// ---------------- 1. transpose x(n,c,s,p) -> X2(n*16+p, s, c) fp32 + fp16 ----------------
__global__ __launch_bounds__(256) void transpose_kernel(const float* __restrict__ x) {
    extern __shared__ float Ts[]; // [16][1025]
    int n  = blockIdx.x >> 4;
    int c0 = (blockIdx.x & 15) * 16;
    int t = threadIdx.x;
    const float* src = x + (size_t)(n*C_ + c0) * (S_*P_);
    for (int idx = t; idx < 16*1024; idx += 256) {
        int i = idx >> 10, sp = idx & 1023;
        Ts[i*1025 + sp] = src[i*1024 + sp];
    }
    __syncthreads();
    for (int idx = t; idx < 16*1024; idx += 256) {
        int sp = idx >> 4, i = idx & 15;
        int s = sp >> 4, p = sp & 15;
        size_t g = (size_t)((n*P_ + p)*S_ + s) * C_ + c0 + i;
        float v = Ts[i*1025 + sp];
        g_X2[g]  = v;
        g_X2f[g] = __float2half_rn(v);
    }
}

// ---------------- 1b. weight transpose + fp16 conversion ----------------
__global__ __launch_bounds__(256) void wconv_kernel(const float* __restrict__ Wq,
                                                    const float* __restrict__ Wk,
                                                    const float* __restrict__ Wv,
                                                    const float* __restrict__ Wo) {
    int g = blockIdx.x*256 + threadIdx.x;   // 0..262143
    int mat = g >> 16, rem = g & 65535;
    int n = rem >> 8, k = rem & 255;
    const float* W = (mat==0) ? Wq : (mat==1) ? Wk : (mat==2) ? Wv : Wo;
    g_Wtf[mat*65536 + n*256 + k] = __float2half_rn(W[k*256 + n]);
}

// ---------------- 2. instance-norm + cosine-sim argmax -> hard_idx ----------------
__global__ __launch_bounds__(256) void assign_kernel(const float* __restrict__ protos) {
    extern __shared__ float sm[];
    float* Xs   = sm;                // 64 x 260
    float* Ps   = Xs + 64*260;       // 4 x 256
    float* mu   = Ps + 4*256;        // 256
    float* rstd = mu + 256;          // 256
    float* rn   = rstd + 256;        // 4
    int p = blockIdx.x & 15;
    int n = blockIdx.x >> 4;
    int b = n*16 + p;
    int t = threadIdx.x;
    const float* xb = g_X2 + (size_t)b * S_ * C_;
    for (int idx = t; idx < S_*C_; idx += 256) {
        int s = idx >> 8, c = idx & 255;
        Xs[s*260 + c] = xb[idx];
    }
    for (int idx = t; idx < K_*C_; idx += 256)
        Ps[idx] = protos[p*K_*C_ + idx];
    __syncthreads();

    int w = t >> 5, lane = t & 31;
    if (w < 4) {
        float ss = 0.f;
        for (int c = lane; c < 256; c += 32) { float v = Ps[w*256 + c]; ss += v*v; }
        #pragma unroll
        for (int o = 16; o; o >>= 1) ss += __shfl_xor_sync(0xffffffffu, ss, o);
        if (lane == 0) rn[w] = rsqrtf(ss);
    }
    {
        int c = t;
        float s1 = 0.f;
        #pragma unroll 8
        for (int s = 0; s < 64; s++) s1 += Xs[s*260 + c];
        float m = s1 * (1.f/64.f);
        float s2 = 0.f;
        #pragma unroll 8
        for (int s = 0; s < 64; s++) { float d = Xs[s*260 + c] - m; s2 += d*d; }
        mu[c] = m;
        rstd[c] = rsqrtf(s2 * (1.f/64.f) + 1e-5f);
    }
    __syncthreads();

    int s = t >> 2, j = t & 3;
    float a0 = 0.f, a1 = 0.f, a2 = 0.f, a3 = 0.f;
    for (int cc = 0; cc < 64; cc++) {
        int c = cc*4 + j;
        float xv = (Xs[s*260 + c] - mu[c]) * rstd[c];
        a0 += xv * Ps[c];
        a1 += xv * Ps[256 + c];
        a2 += xv * Ps[512 + c];
        a3 += xv * Ps[768 + c];
    }
    #pragma unroll
    for (int o = 1; o <= 2; o <<= 1) {
        a0 += __shfl_xor_sync(0xffffffffu, a0, o);
        a1 += __shfl_xor_sync(0xffffffffu, a1, o);
        a2 += __shfl_xor_sync(0xffffffffu, a2, o);
        a3 += __shfl_xor_sync(0xffffffffu, a3, o);
    }
    if (j == 0) {
        float v0 = a0*rn[0], v1 = a1*rn[1], v2 = a2*rn[2], v3 = a3*rn[3];
        int best = 0; float bv = v0;
        if (v1 > bv) { bv = v1; best = 1; }
        if (v2 > bv) { bv = v2; best = 2; }
        if (v3 > bv) { bv = v3; best = 3; }
        g_idx[(p*N_ + n)*S_ + s] = best;
    }
}

// ---------------- 3. per-(n,s) mode over parts ----------------
__global__ __launch_bounds__(256) void mode_kernel(float* __restrict__ out) {
    int t = blockIdx.x*256 + threadIdx.x;   // n*64 + s
    if (t >= N_*S_) return;
    int n = t >> 6, s = t & 63;
    int c0=0,c1=0,c2=0,c3=0;
    #pragma unroll
    for (int p = 0; p < 16; p++) {
        int k = g_idx[(p*N_ + n)*S_ + s];
        c0 += (k==0); c1 += (k==1); c2 += (k==2); c3 += (k==3);
    }
    int best = 0, bc = c0;
    if (c1 > bc) { bc = c1; best = 1; }
    if (c2 > bc) { bc = c2; best = 2; }
    if (c3 > bc) { bc = c3; best = 3; }
    out[N_*C_*P_ + t] = (float)best;
}

// ---------------- 4. HMMA fp16 GEMM: CTA tile 64(M) x 128(N), up to 3 CTAs/SM ----------------
// 8 warps = 2(M) x 4(N), warp tile 32x32. K chunked by 64, 2-stage cp.async.
#define STG_A 0
#define STG_B 8192
#define STG_SZ 24576
#define GEMM_SMEM (2*STG_SZ)

__device__ __forceinline__ void gemm_mainloop(
    const __half* __restrict__ A, const __half* __restrict__ Bt,
    char* smc, int m0, int n0, int tid, int wm, int wn, int lane,
    float acc[2][4][4])
{
    uint32_t sbase = smem_u32(smc);
    #pragma unroll
    for (int i = 0; i < 2; i++)
        #pragma unroll
        for (int j = 0; j < 4; j++)
            #pragma unroll
            for (int q = 0; q < 4; q++) acc[i][j][q] = 0.f;

    auto issue = [&](int kc, int stage) {
        int k0 = kc * 64;
        uint32_t st = sbase + stage*STG_SZ;
        #pragma unroll
        for (int it = 0; it < 2; it++) {
            int idx = tid + it*256;          // 0..511 -> A rows 0..63
            int row = idx >> 3, v = idx & 7;
            uint32_t off = (uint32_t)(row*128 + v*16);
            uint32_t sw = off ^ ((off >> 3) & 0x70);
            cpasync16(st + STG_A + sw, A + (size_t)(m0 + row)*256 + k0 + v*8);
        }
        #pragma unroll
        for (int it = 0; it < 4; it++) {
            int idx = tid + it*256;          // 0..1023 -> B rows 0..127
            int row = idx >> 3, v = idx & 7;
            uint32_t off = (uint32_t)(row*128 + v*16);
            uint32_t sw = off ^ ((off >> 3) & 0x70);
            cpasync16(st + STG_B + sw, Bt + (size_t)(n0 + row)*256 + k0 + v*8);
        }
        asm volatile("cp.async.commit_group;" ::: "memory");
    };

    issue(0, 0);

    for (int kc = 0; kc < 4; kc++) {
        if (kc < 3) {
            issue(kc + 1, (kc + 1) & 1);
            asm volatile("cp.async.wait_group 1;" ::: "memory");
        } else {
            asm volatile("cp.async.wait_group 0;" ::: "memory");
        }
        __syncthreads();

        uint32_t st = sbase + (kc & 1)*STG_SZ;
        uint32_t sA = st + STG_A, sB = st + STG_B;

        #pragma unroll
        for (int kk = 0; kk < 4; kk++) {
            uint32_t a[2][4];
            #pragma unroll
            for (int mi = 0; mi < 2; mi++) {
                int r = wm*32 + mi*16 + (lane & 15);
                uint32_t off = (uint32_t)(r*128 + kk*32 + ((lane >> 4) & 1)*16);
                off ^= (off >> 3) & 0x70;
                ldsm4(a[mi], sA + off);
            }
            uint32_t b[2][4];
            #pragma unroll
            for (int ni2 = 0; ni2 < 2; ni2++) {
                int r = wn*32 + ni2*16 + ((lane >> 4) & 1)*8 + (lane & 7);
                uint32_t off = (uint32_t)(r*128 + kk*32 + ((lane >> 3) & 1)*16);
                off ^= (off >> 3) & 0x70;
                ldsm4(b[ni2], sB + off);
            }
            #pragma unroll
            for (int mi = 0; mi < 2; mi++) {
                #pragma unroll
                for (int ni = 0; ni < 4; ni++) {
                    int ni2 = ni >> 1, hf = (ni & 1)*2;
                    mma16816(acc[mi][ni], a[mi], b[ni2][hf], b[ni2][hf+1]);
                }
            }
        }
        __syncthreads();
    }
}

// QKV variant: fp16 epilogue into g_QKV, mat = n0>>8
__global__ __launch_bounds__(256, 3) void mma_gemm_kernel(
    const __half* __restrict__ A, const __half* __restrict__ Bt,
    const float* __restrict__ b0p, const float* __restrict__ b1p, const float* __restrict__ b2p,
    __half* __restrict__ outF)
{
    extern __shared__ char smc[];
    int tid = threadIdx.x;
    int wid = tid >> 5, lane = tid & 31;
    int wm = wid >> 2, wn = wid & 3;
    int m0 = blockIdx.x * 64;
    int n0 = blockIdx.y * 128;

    float acc[2][4][4];
    gemm_mainloop(A, Bt, smc, m0, n0, tid, wm, wn, lane, acc);

    int trow = lane >> 2, tcol = (lane & 3)*2;
    int mat = n0 >> 8;
    const float* bias = (mat == 0) ? b0p : (mat == 1) ? b1p : b2p;
    int clbase = (n0 & 255) + wn*32 + tcol;
    size_t moff = (size_t)mat * BS_ * C_;
    #pragma unroll
    for (int mi = 0; mi < 2; mi++) {
        #pragma unroll
        for (int ni = 0; ni < 4; ni++) {
            int cl = clbase + ni*8;
            size_t r0 = (size_t)(m0 + wm*32 + mi*16 + trow);
            size_t r1 = r0 + 8;
            *(uint32_t*)(outF + moff + r0*256 + cl) =
                packh2(acc[mi][ni][0] + bias[cl], acc[mi][ni][1] + bias[cl+1]);
            *(uint32_t*)(outF + moff + r1*256 + cl) =
                packh2(acc[mi][ni][2] + bias[cl], acc[mi][ni][3] + bias[cl+1]);
        }
    }
}

// Wo variant: bias + residual, fused assignment-max pooling (one b per CTA)
#define TS_STRIDE 132
__global__ __launch_bounds__(256, 3) void mma_gemm_wo_kernel(
    const __half* __restrict__ A, const __half* __restrict__ Bt,
    const float* __restrict__ bias, const float* __restrict__ res)
{
    extern __shared__ char smc[];
    int tid = threadIdx.x;
    int wid = tid >> 5, lane = tid & 31;
    int wm = wid >> 2, wn = wid & 3;
    int m0 = blockIdx.x * 64;
    int n0 = blockIdx.y * 128;

    float acc[2][4][4];
    gemm_mainloop(A, Bt, smc, m0, n0, tid, wm, wn, lane, acc);

    float* TS = (float*)smc;                        // [64][TS_STRIDE] -> 33792B < 48K
    int* idxs = (int*)(smc + 64*TS_STRIDE*4);       // [64]
    int trow = lane >> 2, tcol = (lane & 3)*2;
    #pragma unroll
    for (int mi = 0; mi < 2; mi++) {
        #pragma unroll
        for (int ni = 0; ni < 4; ni++) {
            int lc = wn*32 + ni*8 + tcol;
            int lr0 = wm*32 + mi*16 + trow;
            int lr1 = lr0 + 8;
            int gc = n0 + lc;
            size_t r0 = (size_t)(m0 + lr0), r1 = (size_t)(m0 + lr1);
            float2 a0 = *(const float2*)(res + r0*256 + gc);
            float2 a1 = *(const float2*)(res + r1*256 + gc);
            TS[lr0*TS_STRIDE + lc]     = acc[mi][ni][0] + bias[gc]   + a0.x;
            TS[lr0*TS_STRIDE + lc + 1] = acc[mi][ni][1] + bias[gc+1] + a0.y;
            TS[lr1*TS_STRIDE + lc]     = acc[mi][ni][2] + bias[gc]   + a1.x;
            TS[lr1*TS_STRIDE + lc + 1] = acc[mi][ni][3] + bias[gc+1] + a1.y;
        }
    }
    int b = m0 >> 6;                 // one (n,p) per CTA
    int n = b >> 4, p = b & 15;
    if (tid < 64)
        idxs[tid] = g_idx[(p*N_ + n)*S_ + tid];
    __syncthreads();

    if (tid < 128) {
        int cl = tid;
        float m[4] = {-FLT_MAX, -FLT_MAX, -FLT_MAX, -FLT_MAX};
        int cnt[4] = {0, 0, 0, 0};
        #pragma unroll 8
        for (int s = 0; s < 64; s++) {
            float v = TS[s*TS_STRIDE + cl];
            int k = idxs[s];
            m[k] = fmaxf(m[k], v);
            cnt[k]++;
        }
        size_t cbase = ((size_t)(p*N_ + n)*4)*256 + n0 + cl;
        #pragma unroll
        for (int k = 0; k < 4; k++) {
            float r = (cnt[k] == 64) ? m[k] : fmaxf(m[k], 0.f);
            g_clu[cbase + (size_t)k*256] = r;
        }
    }
}

// ---------------- 5. HMMA fp16 causal attention: block per (b,h) ----------------
#define AQ 0
#define AK 8192
#define AV 16384

__global__ __launch_bounds__(128) void attn_mma_kernel() {
    __shared__ __align__(16) char smem[24576];
    int bb = blockIdx.x >> 2, h = blockIdx.x & 3;
    int tid = threadIdx.x, lane = tid & 31, wq = tid >> 5;
    size_t gbase = (size_t)bb*64*256 + h*64;

    // Q,K straight (SW128): 2 arrays x 512 chunks
    for (int i = tid; i < 1024; i += 128) {
        int arr = i >> 9, c = i & 511;
        int s = c >> 3, db = c & 7;
        const __half* src = g_QKV + (size_t)arr*BS_*C_;
        uint32_t off = (uint32_t)(s*128 + db*16);
        off ^= (off >> 3) & 0x70;
        *(uint4*)(smem + arr*8192 + off) = *(const uint4*)(src + gbase + (size_t)s*256 + db*8);
    }
    // V transposed Vt[d][s] with rotated j-order (bank-conflict-free)
    for (int i = tid; i < 512; i += 128) {
        int s = i >> 3, db = i & 7;
        const __half* src = g_QKV + (size_t)2*BS_*C_;
        uint4 pk = *(const uint4*)(src + gbase + (size_t)s*256 + db*8);
        const __half* e = (const __half*)&pk;
        #pragma unroll
        for (int jj = 0; jj < 8; jj++) {
            int j = (jj + db) & 7;
            uint32_t off = (uint32_t)((db*8 + j)*128 + s*2);
            off ^= (off >> 3) & 0x70;
            *(__half*)(smem + AV + off) = e[j];
        }
    }
    __syncthreads();

    uint32_t sQ = smem_u32(smem + AQ), sK = smem_u32(smem + AK), sV = smem_u32(smem + AV);

    float sc[8][4];
    #pragma unroll
    for (int i = 0; i < 8; i++)
        #pragma unroll
        for (int j = 0; j < 4; j++) sc[i][j] = 0.f;

    #pragma unroll
    for (int kk = 0; kk < 4; kk++) {
        uint32_t q[4];
        {
            int r = wq*16 + (lane & 15);
            uint32_t off = (uint32_t)(r*128 + kk*32 + ((lane >> 4) & 1)*16);
            off ^= (off >> 3) & 0x70;
            ldsm4(q, sQ + off);
        }
        #pragma unroll
        for (int ni2 = 0; ni2 < 4; ni2++) {
            uint32_t k4[4];
            int r = ni2*16 + ((lane >> 4) & 1)*8 + (lane & 7);
            uint32_t off = (uint32_t)(r*128 + kk*32 + ((lane >> 3) & 1)*16);
            off ^= (off >> 3) & 0x70;
            ldsm4(k4, sK + off);
            mma16816(sc[2*ni2],   q, k4[0], k4[1]);
            mma16816(sc[2*ni2+1], q, k4[2], k4[3]);
        }
    }

    int trow = lane >> 2, tcolb = (lane & 3)*2;
    int q0 = wq*16 + trow, q1 = q0 + 8;
    float mx0 = -FLT_MAX, mx1 = -FLT_MAX;
    #pragma unroll
    for (int ni = 0; ni < 8; ni++) {
        int c0 = ni*8 + tcolb, c1 = c0 + 1;
        float v0 = (c0 <= q0) ? sc[ni][0]*0.125f : -FLT_MAX;
        float v1 = (c1 <= q0) ? sc[ni][1]*0.125f : -FLT_MAX;
        float v2 = (c0 <= q1) ? sc[ni][2]*0.125f : -FLT_MAX;
        float v3 = (c1 <= q1) ? sc[ni][3]*0.125f : -FLT_MAX;
        sc[ni][0] = v0; sc[ni][1] = v1; sc[ni][2] = v2; sc[ni][3] = v3;
        mx0 = fmaxf(mx0, fmaxf(v0, v1));
        mx1 = fmaxf(mx1, fmaxf(v2, v3));
    }
    mx0 = fmaxf(mx0, __shfl_xor_sync(0xffffffffu, mx0, 1));
    mx0 = fmaxf(mx0, __shfl_xor_sync(0xffffffffu, mx0, 2));
    mx1 = fmaxf(mx1, __shfl_xor_sync(0xffffffffu, mx1, 1));
    mx1 = fmaxf(mx1, __shfl_xor_sync(0xffffffffu, mx1, 2));
    float s0 = 0.f, s1 = 0.f;
    #pragma unroll
    for (int ni = 0; ni < 8; ni++) {
        float e0 = (sc[ni][0] > -FLT_MAX) ? expf(sc[ni][0] - mx0) : 0.f;
        float e1 = (sc[ni][1] > -FLT_MAX) ? expf(sc[ni][1] - mx0) : 0.f;
        float e2 = (sc[ni][2] > -FLT_MAX) ? expf(sc[ni][2] - mx1) : 0.f;
        float e3 = (sc[ni][3] > -FLT_MAX) ? expf(sc[ni][3] - mx1) : 0.f;
        sc[ni][0] = e0; sc[ni][1] = e1; sc[ni][2] = e2; sc[ni][3] = e3;
        s0 += e0 + e1;
        s1 += e2 + e3;
    }
    s0 += __shfl_xor_sync(0xffffffffu, s0, 1);
    s0 += __shfl_xor_sync(0xffffffffu, s0, 2);
    s1 += __shfl_xor_sync(0xffffffffu, s1, 1);
    s1 += __shfl_xor_sync(0xffffffffu, s1, 2);
    float i0 = 1.f/s0, i1 = 1.f/s1;
    #pragma unroll
    for (int ni = 0; ni < 8; ni++) {
        sc[ni][0] *= i0; sc[ni][1] *= i0;
        sc[ni][2] *= i1; sc[ni][3] *= i1;
    }

    float o[8][4];
    #pragma unroll
    for (int i = 0; i < 8; i++)
        #pragma unroll
        for (int j = 0; j < 4; j++) o[i][j] = 0.f;

    #pragma unroll
    for (int kt = 0; kt < 4; kt++) {
        uint32_t ph[4];
        ph[0] = packh2(sc[2*kt][0],   sc[2*kt][1]);
        ph[1] = packh2(sc[2*kt][2],   sc[2*kt][3]);
        ph[2] = packh2(sc[2*kt+1][0], sc[2*kt+1][1]);
        ph[3] = packh2(sc[2*kt+1][2], sc[2*kt+1][3]);
        #pragma unroll
        for (int ni2 = 0; ni2 < 4; ni2++) {
            uint32_t v4[4];
            int r = ni2*16 + ((lane >> 4) & 1)*8 + (lane & 7);
            uint32_t off = (uint32_t)(r*128 + kt*32 + ((lane >> 3) & 1)*16);
            off ^= (off >> 3) & 0x70;
            ldsm4(v4, sV + off);
            mma16816(o[2*ni2],   ph, v4[0], v4[1]);
            mma16816(o[2*ni2+1], ph, v4[2], v4[3]);
        }
    }

    size_t r0 = (size_t)bb*64 + wq*16 + trow;
    size_t r1 = r0 + 8;
    #pragma unroll
    for (int ni = 0; ni < 8; ni++) {
        int c = h*64 + ni*8 + tcolb;
        *(uint32_t*)(g_ATT + r0*256 + c) = packh2(o[ni][0], o[ni][1]);
        *(uint32_t*)(g_ATT + r1*256 + c) = packh2(o[ni][2], o[ni][3]);
    }
}

// ---------------- 7. per-part FC: 256 blocks (p x 16 col-tiles) ----------------
__global__ __launch_bounds__(256) void fc_kernel(const float* __restrict__ fcb,
                                                 float* __restrict__ out) {
    __shared__ float As[32*68];
    __shared__ float Bs[32*17];
    int p  = blockIdx.x >> 4;
    int o0 = (blockIdx.x & 15) * 16;
    int t = threadIdx.x;
    int tm = t >> 4, tn = t & 15;
    const float* Ap = g_clu + (size_t)p*N_*1024;
    const float* Bp = fcb  + (size_t)p*1024*256;
    float acc[4] = {0.f, 0.f, 0.f, 0.f};

    for (int k0 = 0; k0 < 1024; k0 += 32) {
        #pragma unroll
        for (int i = 0; i < 8; i++) {
            int e = t + i*256;
            int row = e >> 5, kk = e & 31;
            As[kk*68 + row] = Ap[(size_t)row*1024 + k0 + kk];
        }
        #pragma unroll
        for (int i = 0; i < 2; i++) {
            int e = t + i*256;
            int kk = e >> 4, oc = e & 15;
            Bs[kk*17 + oc] = Bp[(size_t)(k0 + kk)*256 + o0 + oc];
        }
        __syncthreads();
        #pragma unroll
        for (int kk = 0; kk < 32; kk++) {
            float4 a4 = *(const float4*)&As[kk*68 + tm*4];
            float b = Bs[kk*17 + tn];
            acc[0] += a4.x*b; acc[1] += a4.y*b; acc[2] += a4.z*b; acc[3] += a4.w*b;
        }
        __syncthreads();
    }
    #pragma unroll
    for (int i = 0; i < 4; i++) {
        int nrow = tm*4 + i;
        out[(size_t)nrow*C_*P_ + (o0 + tn)*P_ + p] = acc[i];
    }
}

// ---------------- launch ----------------
extern "C" void kernel_launch(void* const* d_in, const int* in_sizes, int n_in,
                              void* d_out, int out_size) {
    const float* x      = (const float*)d_in[0];
    const float* protos = (const float*)d_in[1];
    const float* Wq = (const float*)d_in[2];
    const float* bq = (const float*)d_in[3];
    const float* Wk = (const float*)d_in[4];
    const float* bk = (const float*)d_in[5];
    const float* Wv = (const float*)d_in[6];
    const float* bv = (const float*)d_in[7];
    const float* Wo = (const float*)d_in[8];
    const float* bo = (const float*)d_in[9];
    const float* fcb = (const float*)d_in[10];
    float* out = (float*)d_out;

    float *pX2;
    __half *pX2f, *pATT, *pWtf, *pQKV;
    cudaGetSymbolAddress((void**)&pX2,  g_X2);
    cudaGetSymbolAddress((void**)&pX2f, g_X2f);
    cudaGetSymbolAddress((void**)&pATT, g_ATT);
    cudaGetSymbolAddress((void**)&pWtf, g_Wtf);
    cudaGetSymbolAddress((void**)&pQKV, g_QKV);

    static cudaStream_t s1 = nullptr;
    static cudaEvent_t e0 = nullptr, eT = nullptr, eA = nullptr, eO = nullptr;
    if (!s1) {
        cudaStreamCreateWithFlags(&s1, cudaStreamNonBlocking);
        cudaEventCreateWithFlags(&e0, cudaEventDisableTiming);
        cudaEventCreateWithFlags(&eT, cudaEventDisableTiming);
        cudaEventCreateWithFlags(&eA, cudaEventDisableTiming);
        cudaEventCreateWithFlags(&eO, cudaEventDisableTiming);
    }

    const int TR_SMEM  = 16*1025*4;                          // 65600
    const int AS_SMEM  = (64*260 + 4*256 + 256 + 256 + 4)*4; // 72720
    cudaFuncSetAttribute(transpose_kernel,   cudaFuncAttributeMaxDynamicSharedMemorySize, TR_SMEM);
    cudaFuncSetAttribute(assign_kernel,      cudaFuncAttributeMaxDynamicSharedMemorySize, AS_SMEM);
    cudaFuncSetAttribute(mma_gemm_kernel,    cudaFuncAttributeMaxDynamicSharedMemorySize, GEMM_SMEM);
    cudaFuncSetAttribute(mma_gemm_wo_kernel, cudaFuncAttributeMaxDynamicSharedMemorySize, GEMM_SMEM);

    cudaEventRecord(e0, 0);
    cudaStreamWaitEvent(s1, e0, 0);

    // 1: wconv (s1) — runs under transpose
    wconv_kernel<<<1024, 256, 0, s1>>>(Wq, Wk, Wv, Wo);

    // 2: transpose (s0), 3: assign (s0)
    transpose_kernel<<<1024, 256, TR_SMEM, 0>>>(x);
    cudaEventRecord(eT, 0);
    assign_kernel<<<1024, 256, AS_SMEM, 0>>>(protos);
    cudaEventRecord(eA, 0);

    // 4: QKV GEMM (s1, waits transpose), 5: attention (s1)
    cudaStreamWaitEvent(s1, eT, 0);
    dim3 qkvgrid(BS_/64, 6);
    mma_gemm_kernel<<<qkvgrid, 256, GEMM_SMEM, s1>>>(pX2f, pWtf, bq, bk, bv, pQKV);
    attn_mma_kernel<<<B_*H_, 128, 0, s1>>>();

    // 6: mode (s0)
    mode_kernel<<<16, 256, 0, 0>>>(out);

    // 7: Wo + fused pooling (s1, needs g_idx)
    cudaStreamWaitEvent(s1, eA, 0);
    dim3 ogrid(BS_/64, 2);
    mma_gemm_wo_kernel<<<ogrid, 256, GEMM_SMEM, s1>>>(pATT, pWtf + 3*C_*C_, bo, pX2);
    cudaEventRecord(eO, s1);

    // 8: fc (s0, joins s1)
    cudaStreamWaitEvent(0, eO, 0);
    fc_kernel<<<256, 256, 0, 0>>>(fcb, out);
}

// round 14
// speedup vs baseline: 2.5767x; 1.0250x over previous
#include <cuda_runtime.h>
#include <cuda_fp16.h>
#include <math.h>
#include <float.h>
#include <stdint.h>

#define N_ 64
#define C_ 256
#define S_ 64
#define P_ 16
#define K_ 4
#define H_ 4
#define D_ 64
#define B_  (N_*P_)    /* 1024 */
#define BS_ (B_*S_)    /* 65536 */

// ---------------- scratch (static __device__, no allocations) ----------------
__device__ float  g_X2 [BS_*C_];        // x2: (b, s, c) fp32 (assign + residual)
__device__ __half g_X2f[BS_*C_];        // fp16 of X2
__device__ __half g_QKV[3*BS_*C_];      // Q/K/V fp16 (mat-major)
__device__ __half g_ATT[BS_*C_];        // attention out fp16
__device__ __half g_Wtf[4*C_*C_];       // transposed weights fp16: [mat][n][k]
__device__ int    g_idx[P_*N_*S_];
__device__ float  g_clu[P_*N_*K_*C_];

// ---------------- helpers ----------------
__device__ __forceinline__ uint32_t smem_u32(const void* p) {
    uint32_t a;
    asm("{ .reg .u64 t; cvta.to.shared.u64 t, %1; cvt.u32.u64 %0, t; }" : "=r"(a) : "l"(p));
    return a;
}
__device__ __forceinline__ void ldsm4(uint32_t* r, uint32_t addr) {
    asm volatile("ldmatrix.sync.aligned.m8n8.x4.shared.b16 {%0,%1,%2,%3}, [%4];"
                 : "=r"(r[0]), "=r"(r[1]), "=r"(r[2]), "=r"(r[3]) : "r"(addr));
}
__device__ __forceinline__ void mma16816(float* d, const uint32_t* a, uint32_t b0, uint32_t b1) {
    asm volatile("mma.sync.aligned.m16n8k16.row.col.f32.f16.f16.f32 "
                 "{%0,%1,%2,%3}, {%4,%5,%6,%7}, {%8,%9}, {%0,%1,%2,%3};"
                 : "+f"(d[0]), "+f"(d[1]), "+f"(d[2]), "+f"(d[3])
                 : "r"(a[0]), "r"(a[1]), "r"(a[2]), "r"(a[3]), "r"(b0), "r"(b1));
}
__device__ __forceinline__ void cpasync16(uint32_t saddr, const void* g) {
    asm volatile("cp.async.cg.shared.global [%0], [%1], 16;" :: "r"(saddr), "l"(g) : "memory");
}
__device__ __forceinline__ uint32_t packh2(float a, float b) {
    __half2 h = __floats2half2_rn(a, b);   // .x = a (low half), .y = b
    return *(uint32_t*)&h;
}

// ---------------- 1. transpose x(n,c,s,p) -> X2(n*16+p, s, c) fp32 + fp16 ----------------
__global__ __launch_bounds__(256) void transpose_kernel(const float* __restrict__ x) {
    extern __shared__ float Ts[]; // [16][1025]
    int n  = blockIdx.x >> 4;
    int c0 = (blockIdx.x & 15) * 16;
    int t = threadIdx.x;
    const float* src = x + (size_t)(n*C_ + c0) * (S_*P_);
    for (int idx = t; idx < 16*1024; idx += 256) {
        int i = idx >> 10, sp = idx & 1023;
        Ts[i*1025 + sp] = src[i*1024 + sp];
    }
    __syncthreads();
    for (int idx = t; idx < 16*1024; idx += 256) {
        int sp = idx >> 4, i = idx & 15;
        int s = sp >> 4, p = sp & 15;
        size_t g = (size_t)((n*P_ + p)*S_ + s) * C_ + c0 + i;
        float v = Ts[i*1025 + sp];
        g_X2[g]  = v;
        g_X2f[g] = __float2half_rn(v);
    }
}

// ---------------- 1b. weight transpose + fp16 conversion ----------------
__global__ __launch_bounds__(256) void wconv_kernel(const float* __restrict__ Wq,
                                                    const float* __restrict__ Wk,
                                                    const float* __restrict__ Wv,
                                                    const float* __restrict__ Wo) {
    int g = blockIdx.x*256 + threadIdx.x;   // 0..262143
    int mat = g >> 16, rem = g & 65535;
    int n = rem >> 8, k = rem & 255;
    const float* W = (mat==0) ? Wq : (mat==1) ? Wk : (mat==2) ? Wv : Wo;
    g_Wtf[mat*65536 + n*256 + k] = __float2half_rn(W[k*256 + n]);
}

// ---------------- 2. instance-norm + cosine-sim argmax -> hard_idx ----------------
__global__ __launch_bounds__(256) void assign_kernel(const float* __restrict__ protos) {
    extern __shared__ float sm[];
    float* Xs   = sm;                // 64 x 260
    float* Ps   = Xs + 64*260;       // 4 x 256
    float* mu   = Ps + 4*256;        // 256
    float* rstd = mu + 256;          // 256
    float* rn   = rstd + 256;        // 4
    int p = blockIdx.x & 15;
    int n = blockIdx.x >> 4;
    int b = n*16 + p;
    int t = threadIdx.x;
    const float* xb = g_X2 + (size_t)b * S_ * C_;
    for (int idx = t; idx < S_*C_; idx += 256) {
        int s = idx >> 8, c = idx & 255;
        Xs[s*260 + c] = xb[idx];
    }
    for (int idx = t; idx < K_*C_; idx += 256)
        Ps[idx] = protos[p*K_*C_ + idx];
    __syncthreads();

    int w = t >> 5, lane = t & 31;
    if (w < 4) {
        float ss = 0.f;
        for (int c = lane; c < 256; c += 32) { float v = Ps[w*256 + c]; ss += v*v; }
        #pragma unroll
        for (int o = 16; o; o >>= 1) ss += __shfl_xor_sync(0xffffffffu, ss, o);
        if (lane == 0) rn[w] = rsqrtf(ss);
    }
    {
        int c = t;
        float s1 = 0.f;
        #pragma unroll 8
        for (int s = 0; s < 64; s++) s1 += Xs[s*260 + c];
        float m = s1 * (1.f/64.f);
        float s2 = 0.f;
        #pragma unroll 8
        for (int s = 0; s < 64; s++) { float d = Xs[s*260 + c] - m; s2 += d*d; }
        mu[c] = m;
        rstd[c] = rsqrtf(s2 * (1.f/64.f) + 1e-5f);
    }
    __syncthreads();

    int s = t >> 2, j = t & 3;
    float a0 = 0.f, a1 = 0.f, a2 = 0.f, a3 = 0.f;
    for (int cc = 0; cc < 64; cc++) {
        int c = cc*4 + j;
        float xv = (Xs[s*260 + c] - mu[c]) * rstd[c];
        a0 += xv * Ps[c];
        a1 += xv * Ps[256 + c];
        a2 += xv * Ps[512 + c];
        a3 += xv * Ps[768 + c];
    }
    #pragma unroll
    for (int o = 1; o <= 2; o <<= 1) {
        a0 += __shfl_xor_sync(0xffffffffu, a0, o);
        a1 += __shfl_xor_sync(0xffffffffu, a1, o);
        a2 += __shfl_xor_sync(0xffffffffu, a2, o);
        a3 += __shfl_xor_sync(0xffffffffu, a3, o);
    }
    if (j == 0) {
        float v0 = a0*rn[0], v1 = a1*rn[1], v2 = a2*rn[2], v3 = a3*rn[3];
        int best = 0; float bv = v0;
        if (v1 > bv) { bv = v1; best = 1; }
        if (v2 > bv) { bv = v2; best = 2; }
        if (v3 > bv) { bv = v3; best = 3; }
        g_idx[(p*N_ + n)*S_ + s] = best;
    }
}

// ---------------- 3. per-(n,s) mode over parts ----------------
__global__ __launch_bounds__(256) void mode_kernel(float* __restrict__ out) {
    int t = blockIdx.x*256 + threadIdx.x;   // n*64 + s
    if (t >= N_*S_) return;
    int n = t >> 6, s = t & 63;
    int c0=0,c1=0,c2=0,c3=0;
    #pragma unroll
    for (int p = 0; p < 16; p++) {
        int k = g_idx[(p*N_ + n)*S_ + s];
        c0 += (k==0); c1 += (k==1); c2 += (k==2); c3 += (k==3);
    }
    int best = 0, bc = c0;
    if (c1 > bc) { bc = c1; best = 1; }
    if (c2 > bc) { bc = c2; best = 2; }
    if (c3 > bc) { bc = c3; best = 3; }
    out[N_*C_*P_ + t] = (float)best;
}

// ---------------- 4. HMMA fp16 GEMM: CTA tile 128(M) x 128(N), warp tile 32x64 ----------------
// 8 warps = 4(M) x 2(N). K chunked by 64, 2-stage cp.async. 2 CTAs/SM.
#define STG_A 0
#define STG_B 16384
#define STG_SZ 32768
#define GEMM_SMEM (2*STG_SZ)
#define TS_STRIDE 132
#define WO_SMEM (128*TS_STRIDE*4 + 512)   /* 68096 > GEMM_SMEM */

__device__ __forceinline__ void gemm_mainloop(
    const __half* __restrict__ A, const __half* __restrict__ Bt,
    char* smc, int m0, int n0, int tid, int wm, int wn, int lane,
    float acc[2][8][4])
{
    uint32_t sbase = smem_u32(smc);
    #pragma unroll
    for (int i = 0; i < 2; i++)
        #pragma unroll
        for (int j = 0; j < 8; j++)
            #pragma unroll
            for (int q = 0; q < 4; q++) acc[i][j][q] = 0.f;

    auto issue = [&](int kc, int stage) {
        int k0 = kc * 64;
        uint32_t st = sbase + stage*STG_SZ;
        #pragma unroll
        for (int it = 0; it < 4; it++) {
            int idx = tid + it*256;          // 0..1023 -> A rows 0..127
            int row = idx >> 3, v = idx & 7;
            uint32_t off = (uint32_t)(row*128 + v*16);
            uint32_t sw = off ^ ((off >> 3) & 0x70);
            cpasync16(st + STG_A + sw, A + (size_t)(m0 + row)*256 + k0 + v*8);
        }
        #pragma unroll
        for (int it = 0; it < 4; it++) {
            int idx = tid + it*256;          // 0..1023 -> B rows 0..127
            int row = idx >> 3, v = idx & 7;
            uint32_t off = (uint32_t)(row*128 + v*16);
            uint32_t sw = off ^ ((off >> 3) & 0x70);
            cpasync16(st + STG_B + sw, Bt + (size_t)(n0 + row)*256 + k0 + v*8);
        }
        asm volatile("cp.async.commit_group;" ::: "memory");
    };

    issue(0, 0);

    for (int kc = 0; kc < 4; kc++) {
        if (kc < 3) {
            issue(kc + 1, (kc + 1) & 1);
            asm volatile("cp.async.wait_group 1;" ::: "memory");
        } else {
            asm volatile("cp.async.wait_group 0;" ::: "memory");
        }
        __syncthreads();

        uint32_t st = sbase + (kc & 1)*STG_SZ;
        uint32_t sA = st + STG_A, sB = st + STG_B;

        #pragma unroll
        for (int kk = 0; kk < 4; kk++) {
            uint32_t a[2][4];
            #pragma unroll
            for (int mi = 0; mi < 2; mi++) {
                int r = wm*32 + mi*16 + (lane & 15);
                uint32_t off = (uint32_t)(r*128 + kk*32 + ((lane >> 4) & 1)*16);
                off ^= (off >> 3) & 0x70;
                ldsm4(a[mi], sA + off);
            }
            uint32_t b[4][4];
            #pragma unroll
            for (int ni2 = 0; ni2 < 4; ni2++) {
                int r = wn*64 + ni2*16 + ((lane >> 4) & 1)*8 + (lane & 7);
                uint32_t off = (uint32_t)(r*128 + kk*32 + ((lane >> 3) & 1)*16);
                off ^= (off >> 3) & 0x70;
                ldsm4(b[ni2], sB + off);
            }
            #pragma unroll
            for (int mi = 0; mi < 2; mi++) {
                #pragma unroll
                for (int ni = 0; ni < 8; ni++) {
                    int ni2 = ni >> 1, hf = (ni & 1)*2;
                    mma16816(acc[mi][ni], a[mi], b[ni2][hf], b[ni2][hf+1]);
                }
            }
        }
        __syncthreads();
    }
}

// QKV variant: fp16 epilogue into g_QKV, mat = n0>>8
__global__ __launch_bounds__(256, 2) void mma_gemm_kernel(
    const __half* __restrict__ A, const __half* __restrict__ Bt,
    const float* __restrict__ b0p, const float* __restrict__ b1p, const float* __restrict__ b2p,
    __half* __restrict__ outF)
{
    extern __shared__ char smc[];
    int tid = threadIdx.x;
    int wid = tid >> 5, lane = tid & 31;
    int wm = wid >> 1, wn = wid & 1;
    int m0 = blockIdx.x * 128;
    int n0 = blockIdx.y * 128;

    float acc[2][8][4];
    gemm_mainloop(A, Bt, smc, m0, n0, tid, wm, wn, lane, acc);

    int trow = lane >> 2, tcol = (lane & 3)*2;
    int mat = n0 >> 8;
    const float* bias = (mat == 0) ? b0p : (mat == 1) ? b1p : b2p;
    int clbase = (n0 & 255) + wn*64 + tcol;
    size_t moff = (size_t)mat * BS_ * C_;
    #pragma unroll
    for (int mi = 0; mi < 2; mi++) {
        #pragma unroll
        for (int ni = 0; ni < 8; ni++) {
            int cl = clbase + ni*8;
            size_t r0 = (size_t)(m0 + wm*32 + mi*16 + trow);
            size_t r1 = r0 + 8;
            *(uint32_t*)(outF + moff + r0*256 + cl) =
                packh2(acc[mi][ni][0] + bias[cl], acc[mi][ni][1] + bias[cl+1]);
            *(uint32_t*)(outF + moff + r1*256 + cl) =
                packh2(acc[mi][ni][2] + bias[cl], acc[mi][ni][3] + bias[cl+1]);
        }
    }
}

// Wo variant: bias + residual, fused assignment-max pooling (two b's per CTA)
__global__ __launch_bounds__(256, 2) void mma_gemm_wo_kernel(
    const __half* __restrict__ A, const __half* __restrict__ Bt,
    const float* __restrict__ bias, const float* __restrict__ res)
{
    extern __shared__ char smc[];
    int tid = threadIdx.x;
    int wid = tid >> 5, lane = tid & 31;
    int wm = wid >> 1, wn = wid & 1;
    int m0 = blockIdx.x * 128;
    int n0 = blockIdx.y * 128;

    float acc[2][8][4];
    gemm_mainloop(A, Bt, smc, m0, n0, tid, wm, wn, lane, acc);

    float* TS = (float*)smc;                        // [128][TS_STRIDE]
    int* idxs = (int*)(smc + 128*TS_STRIDE*4);      // [128]
    int trow = lane >> 2, tcol = (lane & 3)*2;
    #pragma unroll
    for (int mi = 0; mi < 2; mi++) {
        #pragma unroll
        for (int ni = 0; ni < 8; ni++) {
            int lc = wn*64 + ni*8 + tcol;
            int lr0 = wm*32 + mi*16 + trow;
            int lr1 = lr0 + 8;
            int gc = n0 + lc;
            size_t r0 = (size_t)(m0 + lr0), r1 = (size_t)(m0 + lr1);
            float2 a0 = *(const float2*)(res + r0*256 + gc);
            float2 a1 = *(const float2*)(res + r1*256 + gc);
            TS[lr0*TS_STRIDE + lc]     = acc[mi][ni][0] + bias[gc]   + a0.x;
            TS[lr0*TS_STRIDE + lc + 1] = acc[mi][ni][1] + bias[gc+1] + a0.y;
            TS[lr1*TS_STRIDE + lc]     = acc[mi][ni][2] + bias[gc]   + a1.x;
            TS[lr1*TS_STRIDE + lc + 1] = acc[mi][ni][3] + bias[gc+1] + a1.y;
        }
    }
    int b0 = m0 >> 6;                // two (n,p) sequences per CTA
    if (tid < 128) {
        int b = b0 + (tid >> 6), s = tid & 63;
        int n = b >> 4, p = b & 15;
        idxs[tid] = g_idx[(p*N_ + n)*S_ + s];
    }
    __syncthreads();

    // pooling: thread per (b_local, col)
    int bl = tid >> 7, cl = tid & 127;
    int b = b0 + bl;
    int n = b >> 4, p = b & 15;
    float m[4] = {-FLT_MAX, -FLT_MAX, -FLT_MAX, -FLT_MAX};
    int cnt[4] = {0, 0, 0, 0};
    #pragma unroll 8
    for (int s = 0; s < 64; s++) {
        float v = TS[(bl*64 + s)*TS_STRIDE + cl];
        int k = idxs[bl*64 + s];
        m[k] = fmaxf(m[k], v);
        cnt[k]++;
    }
    size_t cbase = ((size_t)(p*N_ + n)*4)*256 + n0 + cl;
    #pragma unroll
    for (int k = 0; k < 4; k++) {
        float r = (cnt[k] == 64) ? m[k] : fmaxf(m[k], 0.f);
        g_clu[cbase + (size_t)k*256] = r;
    }
}

// ---------------- 5. HMMA fp16 causal attention: block per (b,h) ----------------
#define AQ 0
#define AK 8192
#define AV 16384

__global__ __launch_bounds__(128) void attn_mma_kernel() {
    __shared__ __align__(16) char smem[24576];
    int bb = blockIdx.x >> 2, h = blockIdx.x & 3;
    int tid = threadIdx.x, lane = tid & 31, wq = tid >> 5;
    size_t gbase = (size_t)bb*64*256 + h*64;

    // Q,K straight (SW128): 2 arrays x 512 chunks
    for (int i = tid; i < 1024; i += 128) {
        int arr = i >> 9, c = i & 511;
        int s = c >> 3, db = c & 7;
        const __half* src = g_QKV + (size_t)arr*BS_*C_;
        uint32_t off = (uint32_t)(s*128 + db*16);
        off ^= (off >> 3) & 0x70;
        *(uint4*)(smem + arr*8192 + off) = *(const uint4*)(src + gbase + (size_t)s*256 + db*8);
    }
    // V transposed Vt[d][s] with rotated j-order (bank-conflict-free)
    for (int i = tid; i < 512; i += 128) {
        int s = i >> 3, db = i & 7;
        const __half* src = g_QKV + (size_t)2*BS_*C_;
        uint4 pk = *(const uint4*)(src + gbase + (size_t)s*256 + db*8);
        const __half* e = (const __half*)&pk;
        #pragma unroll
        for (int jj = 0; jj < 8; jj++) {
            int j = (jj + db) & 7;
            uint32_t off = (uint32_t)((db*8 + j)*128 + s*2);
            off ^= (off >> 3) & 0x70;
            *(__half*)(smem + AV + off) = e[j];
        }
    }
    __syncthreads();

    uint32_t sQ = smem_u32(smem + AQ), sK = smem_u32(smem + AK), sV = smem_u32(smem + AV);

    float sc[8][4];
    #pragma unroll
    for (int i = 0; i < 8; i++)
        #pragma unroll
        for (int j = 0; j < 4; j++) sc[i][j] = 0.f;

    #pragma unroll
    for (int kk = 0; kk < 4; kk++) {
        uint32_t q[4];
        {
            int r = wq*16 + (lane & 15);
            uint32_t off = (uint32_t)(r*128 + kk*32 + ((lane >> 4) & 1)*16);
            off ^= (off >> 3) & 0x70;
            ldsm4(q, sQ + off);
        }
        #pragma unroll
        for (int ni2 = 0; ni2 < 4; ni2++) {
            uint32_t k4[4];
            int r = ni2*16 + ((lane >> 4) & 1)*8 + (lane & 7);
            uint32_t off = (uint32_t)(r*128 + kk*32 + ((lane >> 3) & 1)*16);
            off ^= (off >> 3) & 0x70;
            ldsm4(k4, sK + off);
            mma16816(sc[2*ni2],   q, k4[0], k4[1]);
            mma16816(sc[2*ni2+1], q, k4[2], k4[3]);
        }
    }

    int trow = lane >> 2, tcolb = (lane & 3)*2;
    int q0 = wq*16 + trow, q1 = q0 + 8;
    float mx0 = -FLT_MAX, mx1 = -FLT_MAX;
    #pragma unroll
    for (int ni = 0; ni < 8; ni++) {
        int c0 = ni*8 + tcolb, c1 = c0 + 1;
        float v0 = (c0 <= q0) ? sc[ni][0]*0.125f : -FLT_MAX;
        float v1 = (c1 <= q0) ? sc[ni][1]*0.125f : -FLT_MAX;
        float v2 = (c0 <= q1) ? sc[ni][2]*0.125f : -FLT_MAX;
        float v3 = (c1 <= q1) ? sc[ni][3]*0.125f : -FLT_MAX;
        sc[ni][0] = v0; sc[ni][1] = v1; sc[ni][2] = v2; sc[ni][3] = v3;
        mx0 = fmaxf(mx0, fmaxf(v0, v1));
        mx1 = fmaxf(mx1, fmaxf(v2, v3));
    }
    mx0 = fmaxf(mx0, __shfl_xor_sync(0xffffffffu, mx0, 1));
    mx0 = fmaxf(mx0, __shfl_xor_sync(0xffffffffu, mx0, 2));
    mx1 = fmaxf(mx1, __shfl_xor_sync(0xffffffffu, mx1, 1));
    mx1 = fmaxf(mx1, __shfl_xor_sync(0xffffffffu, mx1, 2));
    float s0 = 0.f, s1 = 0.f;
    #pragma unroll
    for (int ni = 0; ni < 8; ni++) {
        float e0 = (sc[ni][0] > -FLT_MAX) ? expf(sc[ni][0] - mx0) : 0.f;
        float e1 = (sc[ni][1] > -FLT_MAX) ? expf(sc[ni][1] - mx0) : 0.f;
        float e2 = (sc[ni][2] > -FLT_MAX) ? expf(sc[ni][2] - mx1) : 0.f;
        float e3 = (sc[ni][3] > -FLT_MAX) ? expf(sc[ni][3] - mx1) : 0.f;
        sc[ni][0] = e0; sc[ni][1] = e1; sc[ni][2] = e2; sc[ni][3] = e3;
        s0 += e0 + e1;
        s1 += e2 + e3;
    }
    s0 += __shfl_xor_sync(0xffffffffu, s0, 1);
    s0 += __shfl_xor_sync(0xffffffffu, s0, 2);
    s1 += __shfl_xor_sync(0xffffffffu, s1, 1);
    s1 += __shfl_xor_sync(0xffffffffu, s1, 2);
    float i0 = 1.f/s0, i1 = 1.f/s1;
    #pragma unroll
    for (int ni = 0; ni < 8; ni++) {
        sc[ni][0] *= i0; sc[ni][1] *= i0;
        sc[ni][2] *= i1; sc[ni][3] *= i1;
    }

    float o[8][4];
    #pragma unroll
    for (int i = 0; i < 8; i++)
        #pragma unroll
        for (int j = 0; j < 4; j++) o[i][j] = 0.f;

    #pragma unroll
    for (int kt = 0; kt < 4; kt++) {
        uint32_t ph[4];
        ph[0] = packh2(sc[2*kt][0],   sc[2*kt][1]);
        ph[1] = packh2(sc[2*kt][2],   sc[2*kt][3]);
        ph[2] = packh2(sc[2*kt+1][0], sc[2*kt+1][1]);
        ph[3] = packh2(sc[2*kt+1][2], sc[2*kt+1][3]);
        #pragma unroll
        for (int ni2 = 0; ni2 < 4; ni2++) {
            uint32_t v4[4];
            int r = ni2*16 + ((lane >> 4) & 1)*8 + (lane & 7);
            uint32_t off = (uint32_t)(r*128 + kt*32 + ((lane >> 3) & 1)*16);
            off ^= (off >> 3) & 0x70;
            ldsm4(v4, sV + off);
            mma16816(o[2*ni2],   ph, v4[0], v4[1]);
            mma16816(o[2*ni2+1], ph, v4[2], v4[3]);
        }
    }

    size_t r0 = (size_t)bb*64 + wq*16 + trow;
    size_t r1 = r0 + 8;
    #pragma unroll
    for (int ni = 0; ni < 8; ni++) {
        int c = h*64 + ni*8 + tcolb;
        *(uint32_t*)(g_ATT + r0*256 + c) = packh2(o[ni][0], o[ni][1]);
        *(uint32_t*)(g_ATT + r1*256 + c) = packh2(o[ni][2], o[ni][3]);
    }
}

// ---------------- 7. per-part FC: 256 blocks (p x 16 col-tiles) ----------------
__global__ __launch_bounds__(256) void fc_kernel(const float* __restrict__ fcb,
                                                 float* __restrict__ out) {
    __shared__ float As[32*68];
    __shared__ float Bs[32*17];
    int p  = blockIdx.x >> 4;
    int o0 = (blockIdx.x & 15) * 16;
    int t = threadIdx.x;
    int tm = t >> 4, tn = t & 15;
    const float* Ap = g_clu + (size_t)p*N_*1024;
    const float* Bp = fcb  + (size_t)p*1024*256;
    float acc[4] = {0.f, 0.f, 0.f, 0.f};

    for (int k0 = 0; k0 < 1024; k0 += 32) {
        #pragma unroll
        for (int i = 0; i < 8; i++) {
            int e = t + i*256;
            int row = e >> 5, kk = e & 31;
            As[kk*68 + row] = Ap[(size_t)row*1024 + k0 + kk];
        }
        #pragma unroll
        for (int i = 0; i < 2; i++) {
            int e = t + i*256;
            int kk = e >> 4, oc = e & 15;
            Bs[kk*17 + oc] = Bp[(size_t)(k0 + kk)*256 + o0 + oc];
        }
        __syncthreads();
        #pragma unroll
        for (int kk = 0; kk < 32; kk++) {
            float4 a4 = *(const float4*)&As[kk*68 + tm*4];
            float b = Bs[kk*17 + tn];
            acc[0] += a4.x*b; acc[1] += a4.y*b; acc[2] += a4.z*b; acc[3] += a4.w*b;
        }
        __syncthreads();
    }
    #pragma unroll
    for (int i = 0; i < 4; i++) {
        int nrow = tm*4 + i;
        out[(size_t)nrow*C_*P_ + (o0 + tn)*P_ + p] = acc[i];
    }
}

// ---------------- launch ----------------
extern "C" void kernel_launch(void* const* d_in, const int* in_sizes, int n_in,
                              void* d_out, int out_size) {
    const float* x      = (const float*)d_in[0];
    const float* protos = (const float*)d_in[1];
    const float* Wq = (const float*)d_in[2];
    const float* bq = (const float*)d_in[3];
    const float* Wk = (const float*)d_in[4];
    const float* bk = (const float*)d_in[5];
    const float* Wv = (const float*)d_in[6];
    const float* bv = (const float*)d_in[7];
    const float* Wo = (const float*)d_in[8];
    const float* bo = (const float*)d_in[9];
    const float* fcb = (const float*)d_in[10];
    float* out = (float*)d_out;

    float *pX2;
    __half *pX2f, *pATT, *pWtf, *pQKV;
    cudaGetSymbolAddress((void**)&pX2,  g_X2);
    cudaGetSymbolAddress((void**)&pX2f, g_X2f);
    cudaGetSymbolAddress((void**)&pATT, g_ATT);
    cudaGetSymbolAddress((void**)&pWtf, g_Wtf);
    cudaGetSymbolAddress((void**)&pQKV, g_QKV);

    static cudaStream_t s1 = nullptr;
    static cudaEvent_t e0 = nullptr, eT = nullptr, eA = nullptr, eO = nullptr;
    if (!s1) {
        cudaStreamCreateWithFlags(&s1, cudaStreamNonBlocking);
        cudaEventCreateWithFlags(&e0, cudaEventDisableTiming);
        cudaEventCreateWithFlags(&eT, cudaEventDisableTiming);
        cudaEventCreateWithFlags(&eA, cudaEventDisableTiming);
        cudaEventCreateWithFlags(&eO, cudaEventDisableTiming);
    }

    const int TR_SMEM  = 16*1025*4;                          // 65600
    const int AS_SMEM  = (64*260 + 4*256 + 256 + 256 + 4)*4; // 72720
    cudaFuncSetAttribute(transpose_kernel,   cudaFuncAttributeMaxDynamicSharedMemorySize, TR_SMEM);
    cudaFuncSetAttribute(assign_kernel,      cudaFuncAttributeMaxDynamicSharedMemorySize, AS_SMEM);
    cudaFuncSetAttribute(mma_gemm_kernel,    cudaFuncAttributeMaxDynamicSharedMemorySize, GEMM_SMEM);
    cudaFuncSetAttribute(mma_gemm_wo_kernel, cudaFuncAttributeMaxDynamicSharedMemorySize, WO_SMEM);

    cudaEventRecord(e0, 0);
    cudaStreamWaitEvent(s1, e0, 0);

    // 1: wconv (s1) — runs under transpose
    wconv_kernel<<<1024, 256, 0, s1>>>(Wq, Wk, Wv, Wo);

    // 2: transpose (s0), 3: assign (s0)
    transpose_kernel<<<1024, 256, TR_SMEM, 0>>>(x);
    cudaEventRecord(eT, 0);
    assign_kernel<<<1024, 256, AS_SMEM, 0>>>(protos);
    cudaEventRecord(eA, 0);

    // 4: QKV GEMM (s1, waits transpose), 5: attention (s1)
    cudaStreamWaitEvent(s1, eT, 0);
    dim3 qkvgrid(BS_/128, 6);
    mma_gemm_kernel<<<qkvgrid, 256, GEMM_SMEM, s1>>>(pX2f, pWtf, bq, bk, bv, pQKV);
    attn_mma_kernel<<<B_*H_, 128, 0, s1>>>();

    // 6: mode (s0)
    mode_kernel<<<16, 256, 0, 0>>>(out);

    // 7: Wo + fused pooling (s1, needs g_idx)
    cudaStreamWaitEvent(s1, eA, 0);
    dim3 ogrid(BS_/128, 2);
    mma_gemm_wo_kernel<<<ogrid, 256, WO_SMEM, s1>>>(pATT, pWtf + 3*C_*C_, bo, pX2);
    cudaEventRecord(eO, s1);

    // 8: fc (s0, joins s1)
    cudaStreamWaitEvent(0, eO, 0);
    fc_kernel<<<256, 256, 0, 0>>>(fcb, out);
}